// round 9
// baseline (speedup 1.0000x reference)
#include <cuda_runtime.h>
#include <cuda_bf16.h>
#include <cuda_fp16.h>
#include <stdint.h>
#include <math.h>

#define BB 2
#define SS 2048
#define HH 2048
#define NH 16
#define NKV 4
#define HD 128
#define NQKV 3072   // fused QKV output width: 2048 + 512 + 512

// ---------------- scratch (device globals: allocation-free) ----------------
__device__ float g_qkv[(size_t)BB * SS * NQKV];      // fused QKV projection out
// fp16 split GEMM operands (A side: hi+lo; B side: hi only)
__device__ __half g_hs_hi[(size_t)BB * SS * HH];
__device__ __half g_hs_lo[(size_t)BB * SS * HH];
__device__ __half g_qkvw_hi[(size_t)NQKV * HH];      // fused QKV weights
__device__ __half g_ow_hi[(size_t)HH * NH * HD];
// post-norm attention operands (bf16 3-pass, unchanged numerics)
__device__ __nv_bfloat16 g_qhi[(size_t)BB * SS * NH * HD];
__device__ __nv_bfloat16 g_qlo[(size_t)BB * SS * NH * HD];
__device__ __nv_bfloat16 g_khi[(size_t)BB * SS * NKV * HD];
__device__ __nv_bfloat16 g_klo[(size_t)BB * SS * NKV * HD];
__device__ __nv_bfloat16 g_vhi[(size_t)BB * SS * NKV * HD];
__device__ __nv_bfloat16 g_vlo[(size_t)BB * SS * NKV * HD];
// attention output (fp16 hi/lo, feeds O projection)
__device__ __half g_ahi[(size_t)BB * SS * NH * HD];
__device__ __half g_alo[(size_t)BB * SS * NH * HD];

// ===================== warp-MMA helpers =====================
__device__ __forceinline__ uint32_t smem_to_u32(const void* p) {
    uint32_t a;
    asm("{ .reg .u64 t; cvta.to.shared.u64 t, %1; cvt.u32.u64 %0, t; }"
        : "=r"(a) : "l"(p));
    return a;
}
__device__ __forceinline__ void ldsm_x4(uint32_t r[4], uint32_t addr) {
    asm volatile("ldmatrix.sync.aligned.m8n8.x4.shared.b16 {%0,%1,%2,%3}, [%4];"
                 : "=r"(r[0]), "=r"(r[1]), "=r"(r[2]), "=r"(r[3]) : "r"(addr));
}
__device__ __forceinline__ void ldsm_x4_t(uint32_t r[4], uint32_t addr) {
    asm volatile("ldmatrix.sync.aligned.m8n8.x4.trans.shared.b16 {%0,%1,%2,%3}, [%4];"
                 : "=r"(r[0]), "=r"(r[1]), "=r"(r[2]), "=r"(r[3]) : "r"(addr));
}
// bf16 MMA (attention)
__device__ __forceinline__ void mma16816(float c[4], const uint32_t a[4],
                                         const uint32_t b0, const uint32_t b1) {
    asm volatile(
        "mma.sync.aligned.m16n8k16.row.col.f32.bf16.bf16.f32 "
        "{%0,%1,%2,%3}, {%4,%5,%6,%7}, {%8,%9}, {%0,%1,%2,%3};"
        : "+f"(c[0]), "+f"(c[1]), "+f"(c[2]), "+f"(c[3])
        : "r"(a[0]), "r"(a[1]), "r"(a[2]), "r"(a[3]), "r"(b0), "r"(b1));
}
// fp16 MMA (projections)
__device__ __forceinline__ void mma16816h(float c[4], const uint32_t a[4],
                                          const uint32_t b0, const uint32_t b1) {
    asm volatile(
        "mma.sync.aligned.m16n8k16.row.col.f32.f16.f16.f32 "
        "{%0,%1,%2,%3}, {%4,%5,%6,%7}, {%8,%9}, {%0,%1,%2,%3};"
        : "+f"(c[0]), "+f"(c[1]), "+f"(c[2]), "+f"(c[3])
        : "r"(a[0]), "r"(a[1]), "r"(a[2]), "r"(a[3]), "r"(b0), "r"(b1));
}
__device__ __forceinline__ void cp_async16(uint32_t dst, const void* src) {
    asm volatile("cp.async.cg.shared.global [%0], [%1], 16;"
                 :: "r"(dst), "l"(src) : "memory");
}
#define CP_COMMIT() asm volatile("cp.async.commit_group;" ::: "memory")
#define CP_WAIT(n)  asm volatile("cp.async.wait_group %0;" :: "n"(n) : "memory")

// bf16 split (attention path)
__device__ __forceinline__ void split2(float x, float y, uint32_t& hi, uint32_t& lo) {
    __nv_bfloat16 hx = __float2bfloat16_rn(x);
    __nv_bfloat16 hy = __float2bfloat16_rn(y);
    __nv_bfloat16 lx = __float2bfloat16_rn(x - __bfloat162float(hx));
    __nv_bfloat16 ly = __float2bfloat16_rn(y - __bfloat162float(hy));
    hi = (uint32_t)__bfloat16_as_ushort(hx) | ((uint32_t)__bfloat16_as_ushort(hy) << 16);
    lo = (uint32_t)__bfloat16_as_ushort(lx) | ((uint32_t)__bfloat16_as_ushort(ly) << 16);
}
// fp16 split (GEMM path)
__device__ __forceinline__ void split2h(float x, float y, uint32_t& hi, uint32_t& lo) {
    __half hx = __float2half_rn(x);
    __half hy = __float2half_rn(y);
    __half lx = __float2half_rn(x - __half2float(hx));
    __half ly = __float2half_rn(y - __half2float(hy));
    hi = (uint32_t)__half_as_ushort(hx) | ((uint32_t)__half_as_ushort(hy) << 16);
    lo = (uint32_t)__half_as_ushort(lx) | ((uint32_t)__half_as_ushort(ly) << 16);
}

// swizzled byte offset in a [rows x 32 elems] 16-bit tile (64B rows, 4x16B units)
__device__ __forceinline__ uint32_t swz(int row, int c) {
    return (uint32_t)(row * 64 + ((c ^ ((row >> 1) & 3)) << 4));
}
// swizzled byte offset in a [rows x 128 elems] 16-bit tile (256B rows, 16x16B units)
__device__ __forceinline__ uint32_t swz256(int row, int c) {
    return (uint32_t)(row * 256 + ((c ^ (row & 7)) << 4));
}

// ---------------------------------------------------------------------------
// elementwise converters
// ---------------------------------------------------------------------------
__global__ void split_f32h(const float* __restrict__ x,
                           __half* __restrict__ hi, __half* __restrict__ lo)
{
    size_t i = ((size_t)blockIdx.x * blockDim.x + threadIdx.x) * 4;
    float4 f = *(const float4*)(x + i);
    uint2 h, l;
    split2h(f.x, f.y, h.x, l.x);
    split2h(f.z, f.w, h.y, l.y);
    *(uint2*)(hi + i) = h;
    *(uint2*)(lo + i) = l;
}
__global__ void conv_f32h(const float* __restrict__ x, __half* __restrict__ hi)
{
    size_t i = ((size_t)blockIdx.x * blockDim.x + threadIdx.x) * 4;
    float4 f = *(const float4*)(x + i);
    uint2 h;
    h.x = (uint32_t)__half_as_ushort(__float2half_rn(f.x))
        | ((uint32_t)__half_as_ushort(__float2half_rn(f.y)) << 16);
    h.y = (uint32_t)__half_as_ushort(__float2half_rn(f.z))
        | ((uint32_t)__half_as_ushort(__float2half_rn(f.w)) << 16);
    *(uint2*)(hi + i) = h;
}
// V slice of fused QKV -> bf16 hi/lo (compact layout)
__global__ void v_split(const float* __restrict__ qkv,
                        __nv_bfloat16* __restrict__ hi,
                        __nv_bfloat16* __restrict__ lo)
{
    const int row = blockIdx.x, h = blockIdx.y, d = threadIdx.x;
    float f = qkv[(size_t)row * NQKV + 2560 + h * HD + d];
    __nv_bfloat16 hb = __float2bfloat16_rn(f);
    __nv_bfloat16 lb = __float2bfloat16_rn(f - __bfloat162float(hb));
    size_t o = ((size_t)row * NKV + h) * HD + d;
    hi[o] = hb;
    lo[o] = lb;
}

// ---------------------------------------------------------------------------
// fp16 2-pass split GEMM: C[M][N] = (Ahi+Alo)[M][K] * Bhi[N][K]^T (fp32 out)
// BM=BN=128, BK=32, 512 threads (16 warps 4x4), warp tile 32x32.
// 4-stage cp.async pipeline, ONE sync per chunk.
// ---------------------------------------------------------------------------
#define GS_AH 0
#define GS_AL 8192
#define GS_BH 16384
#define GS_STAGE 24576
#define GS_SMEM (4 * GS_STAGE)

__global__ void __launch_bounds__(512) gemm_fp16(
    const __half* __restrict__ Ahi, const __half* __restrict__ Alo,
    const __half* __restrict__ Bhi,
    float* __restrict__ C, int M, int N, int K)
{
    extern __shared__ char smem[];
    const uint32_t sb = smem_to_u32(smem);

    const int t = threadIdx.x;
    const int lane = t & 31, wid = t >> 5;
    const int bm = blockIdx.y * 128, bn = blockIdx.x * 128;
    const int wm = (wid & 3) * 32;
    const int wn = (wid >> 2) * 32;

    const int lrow = t >> 2, lc = t & 3;
    const size_t ga = (size_t)(bm + lrow) * K + lc * 8;
    const size_t gb = (size_t)(bn + lrow) * K + lc * 8;
    const uint32_t st = swz(lrow, lc);
    const int nch = K >> 5;

    auto issue = [&](int ch) {
        uint32_t base = sb + (uint32_t)(ch & 3) * GS_STAGE + st;
        size_t ka = ga + (size_t)ch * 32;
        size_t kb = gb + (size_t)ch * 32;
        cp_async16(base + GS_AH, Ahi + ka);
        cp_async16(base + GS_AL, Alo + ka);
        cp_async16(base + GS_BH, Bhi + kb);
    };

    issue(0); CP_COMMIT();
    issue(1); CP_COMMIT();
    issue(2); CP_COMMIT();

    float acc[2][4][4];
#pragma unroll
    for (int i = 0; i < 2; i++)
#pragma unroll
        for (int j = 0; j < 4; j++)
#pragma unroll
            for (int q = 0; q < 4; q++) acc[i][j][q] = 0.0f;

    for (int ch = 0; ch < nch; ch++) {
        CP_WAIT(2);
        __syncthreads();                    // stage ch visible; stage ch-1 reads done
        if (ch + 3 < nch) { issue(ch + 3); CP_COMMIT(); }

        const uint32_t base = sb + (uint32_t)(ch & 3) * GS_STAGE;
#pragma unroll
        for (int ks = 0; ks < 2; ks++) {
            uint32_t ah[2][4], al[2][4];
#pragma unroll
            for (int mt = 0; mt < 2; mt++) {
                int row = wm + mt * 16 + (lane & 15);
                int c = ks * 2 + (lane >> 4);
                uint32_t off = swz(row, c);
                ldsm_x4(ah[mt], base + GS_AH + off);
                ldsm_x4(al[mt], base + GS_AL + off);
            }
#pragma unroll
            for (int np = 0; np < 2; np++) {
                uint32_t bh[4];
                int row = wn + np * 16 + (lane & 7) + ((lane >> 4) & 1) * 8;
                int c = ks * 2 + ((lane >> 3) & 1);
                uint32_t off = swz(row, c);
                ldsm_x4(bh, base + GS_BH + off);
#pragma unroll
                for (int half = 0; half < 2; half++) {
                    int nt = np * 2 + half, pb = half * 2;
#pragma unroll
                    for (int mt = 0; mt < 2; mt++) {
                        mma16816h(acc[mt][nt], ah[mt], bh[pb], bh[pb + 1]);
                        mma16816h(acc[mt][nt], al[mt], bh[pb], bh[pb + 1]);
                    }
                }
            }
        }
    }

#pragma unroll
    for (int mt = 0; mt < 2; mt++)
#pragma unroll
        for (int nt = 0; nt < 4; nt++) {
            int r0 = bm + wm + mt * 16 + (lane >> 2);
            int c0 = bn + wn + nt * 8 + (lane & 3) * 2;
            float2 v0 = make_float2(acc[mt][nt][0], acc[mt][nt][1]);
            float2 v1 = make_float2(acc[mt][nt][2], acc[mt][nt][3]);
            *(float2*)&C[(size_t)r0 * N + c0] = v0;
            *(float2*)&C[(size_t)(r0 + 8) * N + c0] = v1;
        }
}

// ---------------------------------------------------------------------------
// Fused per-head RMSNorm + RoPE -> split bf16 hi/lo (optionally pre-scaled).
// Reads from fused-QKV layout: x[row*NQKV + coloff + h*HD + d].
// ---------------------------------------------------------------------------
__global__ void rmsnorm_rope(const float* __restrict__ x, const float* __restrict__ w,
                             __nv_bfloat16* __restrict__ hi, __nv_bfloat16* __restrict__ lo,
                             int nheads, int coloff, float prescale)
{
    const int row = blockIdx.x;
    const int h   = blockIdx.y;
    const int s   = row & (SS - 1);
    const int d   = threadIdx.x;

    float val = x[(size_t)row * NQKV + coloff + h * HD + d];

    float ss = val * val;
#pragma unroll
    for (int off = 16; off > 0; off >>= 1)
        ss += __shfl_xor_sync(0xffffffffu, ss, off);

    __shared__ float red[4];
    __shared__ float xs[128];
    const int warp = d >> 5, lane = d & 31;
    if (lane == 0) red[warp] = ss;
    __syncthreads();
    float tot = red[0] + red[1] + red[2] + red[3];
    float xn  = val * rsqrtf(tot * (1.0f / 128.0f) + 1e-5f) * w[d];
    xs[d] = xn;
    __syncthreads();

    const int i = d & 63;
    float inv_freq = expf(-(float)i * (13.122363377404328f / 64.0f));
    float ang = (float)s * inv_freq;
    float sn, cs;
    sincosf(ang, &sn, &cs);

    float other = xs[d ^ 64];
    float res = (d < 64) ? (xn * cs - other * sn) : (xn * cs + other * sn);
    res *= prescale;

    __nv_bfloat16 hb = __float2bfloat16_rn(res);
    __nv_bfloat16 lb = __float2bfloat16_rn(res - __bfloat162float(hb));
    const size_t obase = ((size_t)row * nheads + h) * HD;
    hi[obase + d] = hb;
    lo[obase + d] = lb;
}

// ---------------------------------------------------------------------------
// Tensor-core causal flash attention, split-bf16 (3-pass), GQA.
// BM=128, BN=64, D=128. 256 threads = 8 warps; warp tile m16 x n64.
// K/V double-buffered via cp.async, ONE sync per iteration.
// Epilogue writes fp16 hi/lo (feeds fp16 O projection).
// ---------------------------------------------------------------------------
#define SQ_HI 0
#define SQ_LO 32768
#define KV_BASE 65536
#define KV_STAGE 65536
#define ST_KH 0
#define ST_KL 16384
#define ST_VH 32768
#define ST_VL 49152
#define FL_SMEM (KV_BASE + 2 * KV_STAGE)

__global__ void __launch_bounds__(256) flash_attn_tc(
    const __nv_bfloat16* __restrict__ qhi, const __nv_bfloat16* __restrict__ qlo,
    const __nv_bfloat16* __restrict__ khi, const __nv_bfloat16* __restrict__ klo,
    const __nv_bfloat16* __restrict__ vhi, const __nv_bfloat16* __restrict__ vlo,
    __half* __restrict__ ohi, __half* __restrict__ olo)
{
    extern __shared__ char smem[];
    const uint32_t sb = smem_to_u32(smem);
    const int t = threadIdx.x, lane = t & 31, wid = t >> 5;
    const int qb = gridDim.x - 1 - blockIdx.x;   // heavy blocks first
    const int h = blockIdx.y, b = blockIdx.z;
    const int kvh = h >> 2;
    const int warp_m = wid * 16;
    const int QSTR = NH * HD;
    const int KSTR = NKV * HD;

    const int cr = t >> 4, cc = t & 15;
    const __nv_bfloat16* kh0 = khi + ((size_t)(b * SS)) * KSTR + kvh * HD;
    const __nv_bfloat16* kl0 = klo + ((size_t)(b * SS)) * KSTR + kvh * HD;
    const __nv_bfloat16* vh0 = vhi + ((size_t)(b * SS)) * KSTR + kvh * HD;
    const __nv_bfloat16* vl0 = vlo + ((size_t)(b * SS)) * KSTR + kvh * HD;

    auto issue_kv = [&](int kb) {
        uint32_t stage = sb + KV_BASE + (uint32_t)(kb & 1) * KV_STAGE;
#pragma unroll
        for (int i = 0; i < 4; i++) {
            int r = cr + i * 16;
            size_t g = (size_t)(kb * 64 + r) * KSTR + cc * 8;
            uint32_t s = swz256(r, cc);
            cp_async16(stage + ST_KH + s, kh0 + g);
            cp_async16(stage + ST_KL + s, kl0 + g);
            cp_async16(stage + ST_VH + s, vh0 + g);
            cp_async16(stage + ST_VL + s, vl0 + g);
        }
    };

    issue_kv(0); CP_COMMIT();

    {
        const __nv_bfloat16* qh = qhi + ((size_t)(b * SS + qb * 128)) * QSTR + h * HD;
        const __nv_bfloat16* ql = qlo + ((size_t)(b * SS + qb * 128)) * QSTR + h * HD;
#pragma unroll
        for (int i = 0; i < 8; i++) {
            int u = t + i * 256;
            int r = u >> 4, c = u & 15;
            size_t g = (size_t)r * QSTR + c * 8;
            uint32_t s = swz256(r, c);
            *(uint4*)(smem + SQ_HI + s) = *(const uint4*)(qh + g);
            *(uint4*)(smem + SQ_LO + s) = *(const uint4*)(ql + g);
        }
    }

    float m0 = -INFINITY, m1 = -INFINITY, l0 = 0.0f, l1 = 0.0f;
    float oacc[16][4];
#pragma unroll
    for (int i = 0; i < 16; i++)
#pragma unroll
        for (int j = 0; j < 4; j++) oacc[i][j] = 0.0f;

    const int row_lo = qb * 128 + warp_m + (lane >> 2);
    const int nkb = 2 * qb + 2;

    for (int kb = 0; kb < nkb; kb++) {
        CP_WAIT(0);                  // stage kb complete (only group in flight)
        __syncthreads();             // visible to all; stage kb-1 reads done
        if (kb + 1 < nkb) { issue_kv(kb + 1); CP_COMMIT(); }

        if (kb * 64 > qb * 128 + warp_m + 15) continue;
        const bool need_mask = (kb * 64 + 63 > qb * 128 + warp_m);
        const uint32_t stage = sb + KV_BASE + (uint32_t)(kb & 1) * KV_STAGE;

        float sacc[8][4];
#pragma unroll
        for (int i = 0; i < 8; i++)
#pragma unroll
            for (int j = 0; j < 4; j++) sacc[i][j] = 0.0f;

#pragma unroll
        for (int ks = 0; ks < 8; ks++) {
            uint32_t ah[4], al[4];
            {
                int ar = warp_m + (lane & 15);
                int ac = ks * 2 + (lane >> 4);
                uint32_t off = swz256(ar, ac);
                ldsm_x4(ah, sb + SQ_HI + off);
                ldsm_x4(al, sb + SQ_LO + off);
            }
#pragma unroll
            for (int np = 0; np < 4; np++) {
                uint32_t bh[4], bl[4];
                int br = np * 16 + (lane & 7) + ((lane >> 4) & 1) * 8;
                int bc = ks * 2 + ((lane >> 3) & 1);
                uint32_t off = swz256(br, bc);
                ldsm_x4(bh, stage + ST_KH + off);
                ldsm_x4(bl, stage + ST_KL + off);
#pragma unroll
                for (int half = 0; half < 2; half++) {
                    int nt = np * 2 + half, pb = half * 2;
                    mma16816(sacc[nt], ah, bh[pb], bh[pb + 1]);
                    mma16816(sacc[nt], ah, bl[pb], bl[pb + 1]);
                    mma16816(sacc[nt], al, bh[pb], bh[pb + 1]);
                }
            }
        }

        if (need_mask) {
#pragma unroll
            for (int nt = 0; nt < 8; nt++) {
                int col = kb * 64 + nt * 8 + (lane & 3) * 2;
#pragma unroll
                for (int j = 0; j < 4; j++) {
                    int cc2 = col + (j & 1);
                    int rr = row_lo + ((j >> 1) << 3);
                    if (cc2 > rr) sacc[nt][j] = -INFINITY;
                }
            }
        }

        float mt0 = -INFINITY, mt1 = -INFINITY;
#pragma unroll
        for (int nt = 0; nt < 8; nt++) {
            mt0 = fmaxf(mt0, fmaxf(sacc[nt][0], sacc[nt][1]));
            mt1 = fmaxf(mt1, fmaxf(sacc[nt][2], sacc[nt][3]));
        }
        mt0 = fmaxf(mt0, __shfl_xor_sync(0xffffffffu, mt0, 1));
        mt0 = fmaxf(mt0, __shfl_xor_sync(0xffffffffu, mt0, 2));
        mt1 = fmaxf(mt1, __shfl_xor_sync(0xffffffffu, mt1, 1));
        mt1 = fmaxf(mt1, __shfl_xor_sync(0xffffffffu, mt1, 2));

        float mn0 = fmaxf(m0, mt0), mn1 = fmaxf(m1, mt1);
        float sc0 = __expf(m0 - mn0), sc1 = __expf(m1 - mn1);
        m0 = mn0; m1 = mn1;

        float ps0 = 0.0f, ps1 = 0.0f;
#pragma unroll
        for (int nt = 0; nt < 8; nt++) {
            sacc[nt][0] = __expf(sacc[nt][0] - mn0);
            sacc[nt][1] = __expf(sacc[nt][1] - mn0);
            sacc[nt][2] = __expf(sacc[nt][2] - mn1);
            sacc[nt][3] = __expf(sacc[nt][3] - mn1);
            ps0 += sacc[nt][0] + sacc[nt][1];
            ps1 += sacc[nt][2] + sacc[nt][3];
        }
        ps0 += __shfl_xor_sync(0xffffffffu, ps0, 1);
        ps0 += __shfl_xor_sync(0xffffffffu, ps0, 2);
        ps1 += __shfl_xor_sync(0xffffffffu, ps1, 1);
        ps1 += __shfl_xor_sync(0xffffffffu, ps1, 2);
        l0 = l0 * sc0 + ps0;
        l1 = l1 * sc1 + ps1;

#pragma unroll
        for (int nt = 0; nt < 16; nt++) {
            oacc[nt][0] *= sc0; oacc[nt][1] *= sc0;
            oacc[nt][2] *= sc1; oacc[nt][3] *= sc1;
        }

#pragma unroll
        for (int ks = 0; ks < 4; ks++) {
            uint32_t phi[4], plo[4];
            split2(sacc[2 * ks][0], sacc[2 * ks][1], phi[0], plo[0]);
            split2(sacc[2 * ks][2], sacc[2 * ks][3], phi[1], plo[1]);
            split2(sacc[2 * ks + 1][0], sacc[2 * ks + 1][1], phi[2], plo[2]);
            split2(sacc[2 * ks + 1][2], sacc[2 * ks + 1][3], phi[3], plo[3]);
#pragma unroll
            for (int dp = 0; dp < 8; dp++) {
                uint32_t vh4[4], vl4[4];
                int vr = ks * 16 + (lane & 7) + ((lane >> 3) & 1) * 8;
                int vc = dp * 2 + (lane >> 4);
                uint32_t off = swz256(vr, vc);
                ldsm_x4_t(vh4, stage + ST_VH + off);
                ldsm_x4_t(vl4, stage + ST_VL + off);
                mma16816(oacc[dp * 2], phi, vh4[0], vh4[1]);
                mma16816(oacc[dp * 2], phi, vl4[0], vl4[1]);
                mma16816(oacc[dp * 2], plo, vh4[0], vh4[1]);
                mma16816(oacc[dp * 2 + 1], phi, vh4[2], vh4[3]);
                mma16816(oacc[dp * 2 + 1], phi, vl4[2], vl4[3]);
                mma16816(oacc[dp * 2 + 1], plo, vh4[2], vh4[3]);
            }
        }
    }

    // ---- epilogue: write fp16 hi/lo ----
    float il0 = 1.0f / l0, il1 = 1.0f / l1;
    __half* oh = ohi + ((size_t)(b * SS)) * QSTR + h * HD;
    __half* ol = olo + ((size_t)(b * SS)) * QSTR + h * HD;
    int r0 = qb * 128 + warp_m + (lane >> 2);
#pragma unroll
    for (int nt = 0; nt < 16; nt++) {
        int dim = nt * 8 + (lane & 3) * 2;
        uint32_t h0, l0b, h1, l1b;
        split2h(oacc[nt][0] * il0, oacc[nt][1] * il0, h0, l0b);
        split2h(oacc[nt][2] * il1, oacc[nt][3] * il1, h1, l1b);
        *(uint32_t*)&oh[(size_t)r0 * QSTR + dim] = h0;
        *(uint32_t*)&ol[(size_t)r0 * QSTR + dim] = l0b;
        *(uint32_t*)&oh[(size_t)(r0 + 8) * QSTR + dim] = h1;
        *(uint32_t*)&ol[(size_t)(r0 + 8) * QSTR + dim] = l1b;
    }
}

// ---------------------------------------------------------------------------
extern "C" void kernel_launch(void* const* d_in, const int* in_sizes, int n_in,
                              void* d_out, int out_size)
{
    const float* hs  = (const float*)d_in[0];
    const float* q_w = (const float*)d_in[1];
    const float* k_w = (const float*)d_in[2];
    const float* v_w = (const float*)d_in[3];
    const float* o_w = (const float*)d_in[4];
    const float* qn  = (const float*)d_in[5];
    const float* kn  = (const float*)d_in[6];
    float* out = (float*)d_out;

    float* pqkv;
    __half *hsh, *hsl, *qkvw, *owh, *pah, *pal;
    __nv_bfloat16 *pqh, *pql, *pkh, *pkl, *pvh, *pvl;
    cudaGetSymbolAddress((void**)&pqkv, g_qkv);
    cudaGetSymbolAddress((void**)&hsh, g_hs_hi);
    cudaGetSymbolAddress((void**)&hsl, g_hs_lo);
    cudaGetSymbolAddress((void**)&qkvw, g_qkvw_hi);
    cudaGetSymbolAddress((void**)&owh, g_ow_hi);
    cudaGetSymbolAddress((void**)&pah, g_ahi);
    cudaGetSymbolAddress((void**)&pal, g_alo);
    cudaGetSymbolAddress((void**)&pqh, g_qhi);
    cudaGetSymbolAddress((void**)&pql, g_qlo);
    cudaGetSymbolAddress((void**)&pkh, g_khi);
    cudaGetSymbolAddress((void**)&pkl, g_klo);
    cudaGetSymbolAddress((void**)&pvh, g_vhi);
    cudaGetSymbolAddress((void**)&pvl, g_vlo);

    const int M = BB * SS;     // 4096
    const int K = HH;          // 2048
    const float RSCALE = 0.08838834764831845f;

    // operand conversion: A hi+lo fp16; fused QKV weight hi-only fp16
    split_f32h<<<(M * HH) / 1024, 256>>>(hs, hsh, hsl);
    conv_f32h<<<(NH * HD * HH) / 1024, 256>>>(q_w, qkvw);                    // rows 0..2047
    conv_f32h<<<(NKV * HD * HH) / 1024, 256>>>(k_w, qkvw + (size_t)2048 * HH); // rows 2048..2559
    conv_f32h<<<(NKV * HD * HH) / 1024, 256>>>(v_w, qkvw + (size_t)2560 * HH); // rows 2560..3071
    conv_f32h<<<(HH * NH * HD) / 1024, 256>>>(o_w, owh);

    cudaFuncSetAttribute(gemm_fp16, cudaFuncAttributeMaxDynamicSharedMemorySize,
                         GS_SMEM);

    // fused QKV projection: one GEMM, N = 3072
    gemm_fp16<<<dim3(NQKV / 128, M / 128), 512, GS_SMEM>>>(hsh, hsl, qkvw,
                                                           pqkv, M, NQKV, K);

    // RMSNorm + RoPE -> bf16 hi/lo (Q pre-scaled); V split
    rmsnorm_rope<<<dim3(M, NH), 128>>>(pqkv, qn, pqh, pql, NH, 0, RSCALE);
    rmsnorm_rope<<<dim3(M, NKV), 128>>>(pqkv, kn, pkh, pkl, NKV, 2048, 1.0f);
    v_split<<<dim3(M, NKV), 128>>>(pqkv, pvh, pvl);

    // tensor-core causal flash attention (bf16 3-pass), fp16 hi/lo out
    cudaFuncSetAttribute(flash_attn_tc, cudaFuncAttributeMaxDynamicSharedMemorySize,
                         FL_SMEM);
    flash_attn_tc<<<dim3(SS / 128, NH, BB), 256, FL_SMEM>>>(pqh, pql, pkh, pkl,
                                                            pvh, pvl, pah, pal);

    // output projection (fp16 2-pass)
    gemm_fp16<<<dim3(HH / 128, M / 128), 512, GS_SMEM>>>(pah, pal, owh,
                                                         out, M, HH, K);
}

// round 10
// speedup vs baseline: 1.0510x; 1.0510x over previous
#include <cuda_runtime.h>
#include <cuda_bf16.h>
#include <cuda_fp16.h>
#include <stdint.h>
#include <math.h>

#define BB 2
#define SS 2048
#define HH 2048
#define NH 16
#define NKV 4
#define HD 128
#define NQKV 3072   // fused QKV output width: 2048 + 512 + 512

// ---------------- scratch (device globals: allocation-free) ----------------
__device__ float g_qkv[(size_t)BB * SS * NQKV];      // fused QKV projection out
// fp16 split GEMM operands (A side: hi+lo; B side: hi only)
__device__ __half g_hs_hi[(size_t)BB * SS * HH];
__device__ __half g_hs_lo[(size_t)BB * SS * HH];
__device__ __half g_qkvw_hi[(size_t)NQKV * HH];      // fused QKV weights
__device__ __half g_ow_hi[(size_t)HH * NH * HD];
// post-norm attention operands: Q/K bf16 hi/lo (3-pass QK^T), V fp16 hi (2-pass PV)
__device__ __nv_bfloat16 g_qhi[(size_t)BB * SS * NH * HD];
__device__ __nv_bfloat16 g_qlo[(size_t)BB * SS * NH * HD];
__device__ __nv_bfloat16 g_khi[(size_t)BB * SS * NKV * HD];
__device__ __nv_bfloat16 g_klo[(size_t)BB * SS * NKV * HD];
__device__ __half g_vh[(size_t)BB * SS * NKV * HD];
// attention output (fp16 hi/lo, feeds O projection)
__device__ __half g_ahi[(size_t)BB * SS * NH * HD];
__device__ __half g_alo[(size_t)BB * SS * NH * HD];

// ===================== warp-MMA helpers =====================
__device__ __forceinline__ uint32_t smem_to_u32(const void* p) {
    uint32_t a;
    asm("{ .reg .u64 t; cvta.to.shared.u64 t, %1; cvt.u32.u64 %0, t; }"
        : "=r"(a) : "l"(p));
    return a;
}
__device__ __forceinline__ void ldsm_x4(uint32_t r[4], uint32_t addr) {
    asm volatile("ldmatrix.sync.aligned.m8n8.x4.shared.b16 {%0,%1,%2,%3}, [%4];"
                 : "=r"(r[0]), "=r"(r[1]), "=r"(r[2]), "=r"(r[3]) : "r"(addr));
}
__device__ __forceinline__ void ldsm_x4_t(uint32_t r[4], uint32_t addr) {
    asm volatile("ldmatrix.sync.aligned.m8n8.x4.trans.shared.b16 {%0,%1,%2,%3}, [%4];"
                 : "=r"(r[0]), "=r"(r[1]), "=r"(r[2]), "=r"(r[3]) : "r"(addr));
}
// bf16 MMA (attention QK^T)
__device__ __forceinline__ void mma16816(float c[4], const uint32_t a[4],
                                         const uint32_t b0, const uint32_t b1) {
    asm volatile(
        "mma.sync.aligned.m16n8k16.row.col.f32.bf16.bf16.f32 "
        "{%0,%1,%2,%3}, {%4,%5,%6,%7}, {%8,%9}, {%0,%1,%2,%3};"
        : "+f"(c[0]), "+f"(c[1]), "+f"(c[2]), "+f"(c[3])
        : "r"(a[0]), "r"(a[1]), "r"(a[2]), "r"(a[3]), "r"(b0), "r"(b1));
}
// fp16 MMA (projections + PV)
__device__ __forceinline__ void mma16816h(float c[4], const uint32_t a[4],
                                          const uint32_t b0, const uint32_t b1) {
    asm volatile(
        "mma.sync.aligned.m16n8k16.row.col.f32.f16.f16.f32 "
        "{%0,%1,%2,%3}, {%4,%5,%6,%7}, {%8,%9}, {%0,%1,%2,%3};"
        : "+f"(c[0]), "+f"(c[1]), "+f"(c[2]), "+f"(c[3])
        : "r"(a[0]), "r"(a[1]), "r"(a[2]), "r"(a[3]), "r"(b0), "r"(b1));
}
__device__ __forceinline__ void cp_async16(uint32_t dst, const void* src) {
    asm volatile("cp.async.cg.shared.global [%0], [%1], 16;"
                 :: "r"(dst), "l"(src) : "memory");
}
#define CP_COMMIT() asm volatile("cp.async.commit_group;" ::: "memory")
#define CP_WAIT(n)  asm volatile("cp.async.wait_group %0;" :: "n"(n) : "memory")

// bf16 split (QK path)
__device__ __forceinline__ void split2(float x, float y, uint32_t& hi, uint32_t& lo) {
    __nv_bfloat16 hx = __float2bfloat16_rn(x);
    __nv_bfloat16 hy = __float2bfloat16_rn(y);
    __nv_bfloat16 lx = __float2bfloat16_rn(x - __bfloat162float(hx));
    __nv_bfloat16 ly = __float2bfloat16_rn(y - __bfloat162float(hy));
    hi = (uint32_t)__bfloat16_as_ushort(hx) | ((uint32_t)__bfloat16_as_ushort(hy) << 16);
    lo = (uint32_t)__bfloat16_as_ushort(lx) | ((uint32_t)__bfloat16_as_ushort(ly) << 16);
}
// fp16 split (GEMM + PV path)
__device__ __forceinline__ void split2h(float x, float y, uint32_t& hi, uint32_t& lo) {
    __half hx = __float2half_rn(x);
    __half hy = __float2half_rn(y);
    __half lx = __float2half_rn(x - __half2float(hx));
    __half ly = __float2half_rn(y - __half2float(hy));
    hi = (uint32_t)__half_as_ushort(hx) | ((uint32_t)__half_as_ushort(hy) << 16);
    lo = (uint32_t)__half_as_ushort(lx) | ((uint32_t)__half_as_ushort(ly) << 16);
}

// swizzled byte offset in a [rows x 32 elems] 16-bit tile (64B rows, 4x16B units)
__device__ __forceinline__ uint32_t swz(int row, int c) {
    return (uint32_t)(row * 64 + ((c ^ ((row >> 1) & 3)) << 4));
}
// swizzled byte offset in a [rows x 128 elems] 16-bit tile (256B rows, 16x16B units)
__device__ __forceinline__ uint32_t swz256(int row, int c) {
    return (uint32_t)(row * 256 + ((c ^ (row & 7)) << 4));
}

// ---------------------------------------------------------------------------
// elementwise converters
// ---------------------------------------------------------------------------
__global__ void split_f32h(const float* __restrict__ x,
                           __half* __restrict__ hi, __half* __restrict__ lo)
{
    size_t i = ((size_t)blockIdx.x * blockDim.x + threadIdx.x) * 4;
    float4 f = *(const float4*)(x + i);
    uint2 h, l;
    split2h(f.x, f.y, h.x, l.x);
    split2h(f.z, f.w, h.y, l.y);
    *(uint2*)(hi + i) = h;
    *(uint2*)(lo + i) = l;
}
__global__ void conv_f32h(const float* __restrict__ x, __half* __restrict__ hi)
{
    size_t i = ((size_t)blockIdx.x * blockDim.x + threadIdx.x) * 4;
    float4 f = *(const float4*)(x + i);
    uint2 h;
    h.x = (uint32_t)__half_as_ushort(__float2half_rn(f.x))
        | ((uint32_t)__half_as_ushort(__float2half_rn(f.y)) << 16);
    h.y = (uint32_t)__half_as_ushort(__float2half_rn(f.z))
        | ((uint32_t)__half_as_ushort(__float2half_rn(f.w)) << 16);
    *(uint2*)(hi + i) = h;
}

// ---------------------------------------------------------------------------
// Fused pre-attention kernel: grid (M, NH+NKV+NKV).
//   blockIdx.y <  NH          : Q rmsnorm+rope -> bf16 hi/lo (prescaled)
//   blockIdx.y in [NH, NH+NKV): K rmsnorm+rope -> bf16 hi/lo
//   blockIdx.y >= NH+NKV      : V -> fp16 hi
// ---------------------------------------------------------------------------
__global__ void norm_split(const float* __restrict__ qkv,
                           const float* __restrict__ qn, const float* __restrict__ kn,
                           __nv_bfloat16* __restrict__ qhi, __nv_bfloat16* __restrict__ qlo,
                           __nv_bfloat16* __restrict__ khi, __nv_bfloat16* __restrict__ klo,
                           __half* __restrict__ vh)
{
    const int row = blockIdx.x;
    const int hb  = blockIdx.y;
    const int d   = threadIdx.x;
    const int s   = row & (SS - 1);

    if (hb >= NH + NKV) {
        // V convert
        const int h = hb - NH - NKV;
        float f = qkv[(size_t)row * NQKV + 2560 + h * HD + d];
        vh[((size_t)row * NKV + h) * HD + d] = __float2half_rn(f);
        return;
    }

    const bool isQ = (hb < NH);
    const int h = isQ ? hb : hb - NH;
    const int coloff = isQ ? 0 : 2048;
    const float* w = isQ ? qn : kn;
    const float prescale = isQ ? 0.08838834764831845f : 1.0f;
    const int nheads = isQ ? NH : NKV;
    __nv_bfloat16* hi = isQ ? qhi : khi;
    __nv_bfloat16* lo = isQ ? qlo : klo;

    float val = qkv[(size_t)row * NQKV + coloff + h * HD + d];

    float ss = val * val;
#pragma unroll
    for (int off = 16; off > 0; off >>= 1)
        ss += __shfl_xor_sync(0xffffffffu, ss, off);

    __shared__ float red[4];
    __shared__ float xs[128];
    const int warp = d >> 5, lane = d & 31;
    if (lane == 0) red[warp] = ss;
    __syncthreads();
    float tot = red[0] + red[1] + red[2] + red[3];
    float xn  = val * rsqrtf(tot * (1.0f / 128.0f) + 1e-5f) * w[d];
    xs[d] = xn;
    __syncthreads();

    const int i = d & 63;
    float inv_freq = expf(-(float)i * (13.122363377404328f / 64.0f));
    float ang = (float)s * inv_freq;
    float sn, cs;
    sincosf(ang, &sn, &cs);

    float other = xs[d ^ 64];
    float res = (d < 64) ? (xn * cs - other * sn) : (xn * cs + other * sn);
    res *= prescale;

    __nv_bfloat16 hbv = __float2bfloat16_rn(res);
    __nv_bfloat16 lbv = __float2bfloat16_rn(res - __bfloat162float(hbv));
    const size_t obase = ((size_t)row * nheads + h) * HD;
    hi[obase + d] = hbv;
    lo[obase + d] = lbv;
}

// ---------------------------------------------------------------------------
// fp16 2-pass split GEMM: C[M][N] = (Ahi+Alo)[M][K] * Bhi[N][K]^T (fp32 out)
// BM=BN=128, BK=32, 512 threads (16 warps 4x4), warp tile 32x32.
// 4-stage cp.async pipeline, ONE sync per chunk.
// ---------------------------------------------------------------------------
#define GS_AH 0
#define GS_AL 8192
#define GS_BH 16384
#define GS_STAGE 24576
#define GS_SMEM (4 * GS_STAGE)

__global__ void __launch_bounds__(512) gemm_fp16(
    const __half* __restrict__ Ahi, const __half* __restrict__ Alo,
    const __half* __restrict__ Bhi,
    float* __restrict__ C, int M, int N, int K)
{
    extern __shared__ char smem[];
    const uint32_t sb = smem_to_u32(smem);

    const int t = threadIdx.x;
    const int lane = t & 31, wid = t >> 5;
    const int bm = blockIdx.y * 128, bn = blockIdx.x * 128;
    const int wm = (wid & 3) * 32;
    const int wn = (wid >> 2) * 32;

    const int lrow = t >> 2, lc = t & 3;
    const size_t ga = (size_t)(bm + lrow) * K + lc * 8;
    const size_t gb = (size_t)(bn + lrow) * K + lc * 8;
    const uint32_t st = swz(lrow, lc);
    const int nch = K >> 5;

    auto issue = [&](int ch) {
        uint32_t base = sb + (uint32_t)(ch & 3) * GS_STAGE + st;
        size_t ka = ga + (size_t)ch * 32;
        size_t kb = gb + (size_t)ch * 32;
        cp_async16(base + GS_AH, Ahi + ka);
        cp_async16(base + GS_AL, Alo + ka);
        cp_async16(base + GS_BH, Bhi + kb);
    };

    issue(0); CP_COMMIT();
    issue(1); CP_COMMIT();
    issue(2); CP_COMMIT();

    float acc[2][4][4];
#pragma unroll
    for (int i = 0; i < 2; i++)
#pragma unroll
        for (int j = 0; j < 4; j++)
#pragma unroll
            for (int q = 0; q < 4; q++) acc[i][j][q] = 0.0f;

    for (int ch = 0; ch < nch; ch++) {
        CP_WAIT(2);
        __syncthreads();
        if (ch + 3 < nch) { issue(ch + 3); CP_COMMIT(); }

        const uint32_t base = sb + (uint32_t)(ch & 3) * GS_STAGE;
#pragma unroll
        for (int ks = 0; ks < 2; ks++) {
            uint32_t ah[2][4], al[2][4];
#pragma unroll
            for (int mt = 0; mt < 2; mt++) {
                int row = wm + mt * 16 + (lane & 15);
                int c = ks * 2 + (lane >> 4);
                uint32_t off = swz(row, c);
                ldsm_x4(ah[mt], base + GS_AH + off);
                ldsm_x4(al[mt], base + GS_AL + off);
            }
#pragma unroll
            for (int np = 0; np < 2; np++) {
                uint32_t bh[4];
                int row = wn + np * 16 + (lane & 7) + ((lane >> 4) & 1) * 8;
                int c = ks * 2 + ((lane >> 3) & 1);
                uint32_t off = swz(row, c);
                ldsm_x4(bh, base + GS_BH + off);
#pragma unroll
                for (int half = 0; half < 2; half++) {
                    int nt = np * 2 + half, pb = half * 2;
#pragma unroll
                    for (int mt = 0; mt < 2; mt++) {
                        mma16816h(acc[mt][nt], ah[mt], bh[pb], bh[pb + 1]);
                        mma16816h(acc[mt][nt], al[mt], bh[pb], bh[pb + 1]);
                    }
                }
            }
        }
    }

#pragma unroll
    for (int mt = 0; mt < 2; mt++)
#pragma unroll
        for (int nt = 0; nt < 4; nt++) {
            int r0 = bm + wm + mt * 16 + (lane >> 2);
            int c0 = bn + wn + nt * 8 + (lane & 3) * 2;
            float2 v0 = make_float2(acc[mt][nt][0], acc[mt][nt][1]);
            float2 v1 = make_float2(acc[mt][nt][2], acc[mt][nt][3]);
            *(float2*)&C[(size_t)r0 * N + c0] = v0;
            *(float2*)&C[(size_t)(r0 + 8) * N + c0] = v1;
        }
}

// ---------------------------------------------------------------------------
// Tensor-core causal flash attention, GQA.
// QK^T: bf16 3-pass. PV: fp16 2-pass (P hi+lo x V hi).
// BM=128, BN=64, D=128. 256 threads = 8 warps; warp tile m16 x n64.
// K/V double-buffered via cp.async, one sync per iteration.
// ---------------------------------------------------------------------------
#define SQ_HI 0
#define SQ_LO 32768
#define KV_BASE 65536
#define ST_KH 0
#define ST_KL 16384
#define ST_VH 32768
#define KV_STAGE 49152
#define FL_SMEM (KV_BASE + 2 * KV_STAGE)

__global__ void __launch_bounds__(256) flash_attn_tc(
    const __nv_bfloat16* __restrict__ qhi, const __nv_bfloat16* __restrict__ qlo,
    const __nv_bfloat16* __restrict__ khi, const __nv_bfloat16* __restrict__ klo,
    const __half* __restrict__ vh,
    __half* __restrict__ ohi, __half* __restrict__ olo)
{
    extern __shared__ char smem[];
    const uint32_t sb = smem_to_u32(smem);
    const int t = threadIdx.x, lane = t & 31, wid = t >> 5;
    const int qb = gridDim.x - 1 - blockIdx.x;   // heavy blocks first
    const int h = blockIdx.y, b = blockIdx.z;
    const int kvh = h >> 2;
    const int warp_m = wid * 16;
    const int QSTR = NH * HD;
    const int KSTR = NKV * HD;

    const int cr = t >> 4, cc = t & 15;
    const __nv_bfloat16* kh0 = khi + ((size_t)(b * SS)) * KSTR + kvh * HD;
    const __nv_bfloat16* kl0 = klo + ((size_t)(b * SS)) * KSTR + kvh * HD;
    const __half* vh0 = vh + ((size_t)(b * SS)) * KSTR + kvh * HD;

    auto issue_kv = [&](int kb) {
        uint32_t stage = sb + KV_BASE + (uint32_t)(kb & 1) * KV_STAGE;
#pragma unroll
        for (int i = 0; i < 4; i++) {
            int r = cr + i * 16;
            size_t g = (size_t)(kb * 64 + r) * KSTR + cc * 8;
            uint32_t s = swz256(r, cc);
            cp_async16(stage + ST_KH + s, kh0 + g);
            cp_async16(stage + ST_KL + s, kl0 + g);
            cp_async16(stage + ST_VH + s, vh0 + g);
        }
    };

    issue_kv(0); CP_COMMIT();

    {
        const __nv_bfloat16* qh = qhi + ((size_t)(b * SS + qb * 128)) * QSTR + h * HD;
        const __nv_bfloat16* ql = qlo + ((size_t)(b * SS + qb * 128)) * QSTR + h * HD;
#pragma unroll
        for (int i = 0; i < 8; i++) {
            int u = t + i * 256;
            int r = u >> 4, c = u & 15;
            size_t g = (size_t)r * QSTR + c * 8;
            uint32_t s = swz256(r, c);
            *(uint4*)(smem + SQ_HI + s) = *(const uint4*)(qh + g);
            *(uint4*)(smem + SQ_LO + s) = *(const uint4*)(ql + g);
        }
    }

    float m0 = -INFINITY, m1 = -INFINITY, l0 = 0.0f, l1 = 0.0f;
    float oacc[16][4];
#pragma unroll
    for (int i = 0; i < 16; i++)
#pragma unroll
        for (int j = 0; j < 4; j++) oacc[i][j] = 0.0f;

    const int row_lo = qb * 128 + warp_m + (lane >> 2);
    const int nkb = 2 * qb + 2;

    for (int kb = 0; kb < nkb; kb++) {
        CP_WAIT(0);
        __syncthreads();
        if (kb + 1 < nkb) { issue_kv(kb + 1); CP_COMMIT(); }

        if (kb * 64 > qb * 128 + warp_m + 15) continue;
        const bool need_mask = (kb * 64 + 63 > qb * 128 + warp_m);
        const uint32_t stage = sb + KV_BASE + (uint32_t)(kb & 1) * KV_STAGE;

        float sacc[8][4];
#pragma unroll
        for (int i = 0; i < 8; i++)
#pragma unroll
            for (int j = 0; j < 4; j++) sacc[i][j] = 0.0f;

#pragma unroll
        for (int ks = 0; ks < 8; ks++) {
            uint32_t ah[4], al[4];
            {
                int ar = warp_m + (lane & 15);
                int ac = ks * 2 + (lane >> 4);
                uint32_t off = swz256(ar, ac);
                ldsm_x4(ah, sb + SQ_HI + off);
                ldsm_x4(al, sb + SQ_LO + off);
            }
#pragma unroll
            for (int np = 0; np < 4; np++) {
                uint32_t bh[4], bl[4];
                int br = np * 16 + (lane & 7) + ((lane >> 4) & 1) * 8;
                int bc = ks * 2 + ((lane >> 3) & 1);
                uint32_t off = swz256(br, bc);
                ldsm_x4(bh, stage + ST_KH + off);
                ldsm_x4(bl, stage + ST_KL + off);
#pragma unroll
                for (int half = 0; half < 2; half++) {
                    int nt = np * 2 + half, pb = half * 2;
                    mma16816(sacc[nt], ah, bh[pb], bh[pb + 1]);
                    mma16816(sacc[nt], ah, bl[pb], bl[pb + 1]);
                    mma16816(sacc[nt], al, bh[pb], bh[pb + 1]);
                }
            }
        }

        if (need_mask) {
#pragma unroll
            for (int nt = 0; nt < 8; nt++) {
                int col = kb * 64 + nt * 8 + (lane & 3) * 2;
#pragma unroll
                for (int j = 0; j < 4; j++) {
                    int cc2 = col + (j & 1);
                    int rr = row_lo + ((j >> 1) << 3);
                    if (cc2 > rr) sacc[nt][j] = -INFINITY;
                }
            }
        }

        float mt0 = -INFINITY, mt1 = -INFINITY;
#pragma unroll
        for (int nt = 0; nt < 8; nt++) {
            mt0 = fmaxf(mt0, fmaxf(sacc[nt][0], sacc[nt][1]));
            mt1 = fmaxf(mt1, fmaxf(sacc[nt][2], sacc[nt][3]));
        }
        mt0 = fmaxf(mt0, __shfl_xor_sync(0xffffffffu, mt0, 1));
        mt0 = fmaxf(mt0, __shfl_xor_sync(0xffffffffu, mt0, 2));
        mt1 = fmaxf(mt1, __shfl_xor_sync(0xffffffffu, mt1, 1));
        mt1 = fmaxf(mt1, __shfl_xor_sync(0xffffffffu, mt1, 2));

        float mn0 = fmaxf(m0, mt0), mn1 = fmaxf(m1, mt1);
        float sc0 = __expf(m0 - mn0), sc1 = __expf(m1 - mn1);
        m0 = mn0; m1 = mn1;

        float ps0 = 0.0f, ps1 = 0.0f;
#pragma unroll
        for (int nt = 0; nt < 8; nt++) {
            sacc[nt][0] = __expf(sacc[nt][0] - mn0);
            sacc[nt][1] = __expf(sacc[nt][1] - mn0);
            sacc[nt][2] = __expf(sacc[nt][2] - mn1);
            sacc[nt][3] = __expf(sacc[nt][3] - mn1);
            ps0 += sacc[nt][0] + sacc[nt][1];
            ps1 += sacc[nt][2] + sacc[nt][3];
        }
        ps0 += __shfl_xor_sync(0xffffffffu, ps0, 1);
        ps0 += __shfl_xor_sync(0xffffffffu, ps0, 2);
        ps1 += __shfl_xor_sync(0xffffffffu, ps1, 1);
        ps1 += __shfl_xor_sync(0xffffffffu, ps1, 2);
        l0 = l0 * sc0 + ps0;
        l1 = l1 * sc1 + ps1;

#pragma unroll
        for (int nt = 0; nt < 16; nt++) {
            oacc[nt][0] *= sc0; oacc[nt][1] *= sc0;
            oacc[nt][2] *= sc1; oacc[nt][3] *= sc1;
        }

        // ---- PV: fp16 2-pass (P hi+lo x V hi) ----
#pragma unroll
        for (int ks = 0; ks < 4; ks++) {
            uint32_t phi[4], plo[4];
            split2h(sacc[2 * ks][0], sacc[2 * ks][1], phi[0], plo[0]);
            split2h(sacc[2 * ks][2], sacc[2 * ks][3], phi[1], plo[1]);
            split2h(sacc[2 * ks + 1][0], sacc[2 * ks + 1][1], phi[2], plo[2]);
            split2h(sacc[2 * ks + 1][2], sacc[2 * ks + 1][3], phi[3], plo[3]);
#pragma unroll
            for (int dp = 0; dp < 8; dp++) {
                uint32_t vh4[4];
                int vr = ks * 16 + (lane & 7) + ((lane >> 3) & 1) * 8;
                int vc = dp * 2 + (lane >> 4);
                uint32_t off = swz256(vr, vc);
                ldsm_x4_t(vh4, stage + ST_VH + off);
                mma16816h(oacc[dp * 2], phi, vh4[0], vh4[1]);
                mma16816h(oacc[dp * 2], plo, vh4[0], vh4[1]);
                mma16816h(oacc[dp * 2 + 1], phi, vh4[2], vh4[3]);
                mma16816h(oacc[dp * 2 + 1], plo, vh4[2], vh4[3]);
            }
        }
    }

    // ---- epilogue: write fp16 hi/lo ----
    float il0 = 1.0f / l0, il1 = 1.0f / l1;
    __half* oh = ohi + ((size_t)(b * SS)) * QSTR + h * HD;
    __half* ol = olo + ((size_t)(b * SS)) * QSTR + h * HD;
    int r0 = qb * 128 + warp_m + (lane >> 2);
#pragma unroll
    for (int nt = 0; nt < 16; nt++) {
        int dim = nt * 8 + (lane & 3) * 2;
        uint32_t h0, l0b, h1, l1b;
        split2h(oacc[nt][0] * il0, oacc[nt][1] * il0, h0, l0b);
        split2h(oacc[nt][2] * il1, oacc[nt][3] * il1, h1, l1b);
        *(uint32_t*)&oh[(size_t)r0 * QSTR + dim] = h0;
        *(uint32_t*)&ol[(size_t)r0 * QSTR + dim] = l0b;
        *(uint32_t*)&oh[(size_t)(r0 + 8) * QSTR + dim] = h1;
        *(uint32_t*)&ol[(size_t)(r0 + 8) * QSTR + dim] = l1b;
    }
}

// ---------------------------------------------------------------------------
extern "C" void kernel_launch(void* const* d_in, const int* in_sizes, int n_in,
                              void* d_out, int out_size)
{
    const float* hs  = (const float*)d_in[0];
    const float* q_w = (const float*)d_in[1];
    const float* k_w = (const float*)d_in[2];
    const float* v_w = (const float*)d_in[3];
    const float* o_w = (const float*)d_in[4];
    const float* qn  = (const float*)d_in[5];
    const float* kn  = (const float*)d_in[6];
    float* out = (float*)d_out;

    float* pqkv;
    __half *hsh, *hsl, *qkvw, *owh, *pah, *pal, *pvh;
    __nv_bfloat16 *pqh, *pql, *pkh, *pkl;
    cudaGetSymbolAddress((void**)&pqkv, g_qkv);
    cudaGetSymbolAddress((void**)&hsh, g_hs_hi);
    cudaGetSymbolAddress((void**)&hsl, g_hs_lo);
    cudaGetSymbolAddress((void**)&qkvw, g_qkvw_hi);
    cudaGetSymbolAddress((void**)&owh, g_ow_hi);
    cudaGetSymbolAddress((void**)&pah, g_ahi);
    cudaGetSymbolAddress((void**)&pal, g_alo);
    cudaGetSymbolAddress((void**)&pqh, g_qhi);
    cudaGetSymbolAddress((void**)&pql, g_qlo);
    cudaGetSymbolAddress((void**)&pkh, g_khi);
    cudaGetSymbolAddress((void**)&pkl, g_klo);
    cudaGetSymbolAddress((void**)&pvh, g_vh);

    const int M = BB * SS;     // 4096
    const int K = HH;          // 2048

    // operand conversion: A hi+lo fp16; fused QKV weight hi-only fp16
    split_f32h<<<(M * HH) / 1024, 256>>>(hs, hsh, hsl);
    conv_f32h<<<(NH * HD * HH) / 1024, 256>>>(q_w, qkvw);
    conv_f32h<<<(NKV * HD * HH) / 1024, 256>>>(k_w, qkvw + (size_t)2048 * HH);
    conv_f32h<<<(NKV * HD * HH) / 1024, 256>>>(v_w, qkvw + (size_t)2560 * HH);
    conv_f32h<<<(HH * NH * HD) / 1024, 256>>>(o_w, owh);

    cudaFuncSetAttribute(gemm_fp16, cudaFuncAttributeMaxDynamicSharedMemorySize,
                         GS_SMEM);

    // fused QKV projection: one GEMM, N = 3072
    gemm_fp16<<<dim3(NQKV / 128, M / 128), 512, GS_SMEM>>>(hsh, hsl, qkvw,
                                                           pqkv, M, NQKV, K);

    // fused rmsnorm+rope (Q,K) + V convert: one launch
    norm_split<<<dim3(M, NH + NKV + NKV), 128>>>(pqkv, qn, kn,
                                                 pqh, pql, pkh, pkl, pvh);

    // tensor-core causal flash attention (QK bf16 3-pass, PV fp16 2-pass)
    cudaFuncSetAttribute(flash_attn_tc, cudaFuncAttributeMaxDynamicSharedMemorySize,
                         FL_SMEM);
    flash_attn_tc<<<dim3(SS / 128, NH, BB), 256, FL_SMEM>>>(pqh, pql, pkh, pkl,
                                                            pvh, pah, pal);

    // output projection (fp16 2-pass)
    gemm_fp16<<<dim3(HH / 128, M / 128), 512, GS_SMEM>>>(pah, pal, owh,
                                                         out, M, HH, K);
}

// round 11
// speedup vs baseline: 1.1103x; 1.0564x over previous
#include <cuda_runtime.h>
#include <cuda_bf16.h>
#include <cuda_fp16.h>
#include <stdint.h>
#include <math.h>

#define BB 2
#define SS 2048
#define HH 2048
#define NH 16
#define NKV 4
#define HD 128
#define NQKV 3072   // fused QKV output width: 2048 + 512 + 512

// ---------------- scratch (device globals: allocation-free) ----------------
__device__ float g_qkv[(size_t)BB * SS * NQKV];      // fused QKV projection out
// fp16 split GEMM operands (A side: hi+lo; B side: hi only)
__device__ __half g_hs_hi[(size_t)BB * SS * HH];
__device__ __half g_hs_lo[(size_t)BB * SS * HH];
__device__ __half g_qkvw_hi[(size_t)NQKV * HH];      // fused QKV weights
__device__ __half g_ow_hi[(size_t)HH * NH * HD];
// post-norm attention operands: Q fp16 hi/lo, K fp16 hi, V fp16 hi (all 2-pass)
__device__ __half g_qhi[(size_t)BB * SS * NH * HD];
__device__ __half g_qlo[(size_t)BB * SS * NH * HD];
__device__ __half g_kh[(size_t)BB * SS * NKV * HD];
__device__ __half g_vh[(size_t)BB * SS * NKV * HD];
// attention output (fp16 hi/lo, feeds O projection)
__device__ __half g_ahi[(size_t)BB * SS * NH * HD];
__device__ __half g_alo[(size_t)BB * SS * NH * HD];

// ===================== warp-MMA helpers =====================
__device__ __forceinline__ uint32_t smem_to_u32(const void* p) {
    uint32_t a;
    asm("{ .reg .u64 t; cvta.to.shared.u64 t, %1; cvt.u32.u64 %0, t; }"
        : "=r"(a) : "l"(p));
    return a;
}
__device__ __forceinline__ void ldsm_x4(uint32_t r[4], uint32_t addr) {
    asm volatile("ldmatrix.sync.aligned.m8n8.x4.shared.b16 {%0,%1,%2,%3}, [%4];"
                 : "=r"(r[0]), "=r"(r[1]), "=r"(r[2]), "=r"(r[3]) : "r"(addr));
}
__device__ __forceinline__ void ldsm_x4_t(uint32_t r[4], uint32_t addr) {
    asm volatile("ldmatrix.sync.aligned.m8n8.x4.trans.shared.b16 {%0,%1,%2,%3}, [%4];"
                 : "=r"(r[0]), "=r"(r[1]), "=r"(r[2]), "=r"(r[3]) : "r"(addr));
}
// fp16 MMA (projections + attention)
__device__ __forceinline__ void mma16816h(float c[4], const uint32_t a[4],
                                          const uint32_t b0, const uint32_t b1) {
    asm volatile(
        "mma.sync.aligned.m16n8k16.row.col.f32.f16.f16.f32 "
        "{%0,%1,%2,%3}, {%4,%5,%6,%7}, {%8,%9}, {%0,%1,%2,%3};"
        : "+f"(c[0]), "+f"(c[1]), "+f"(c[2]), "+f"(c[3])
        : "r"(a[0]), "r"(a[1]), "r"(a[2]), "r"(a[3]), "r"(b0), "r"(b1));
}
__device__ __forceinline__ void cp_async16(uint32_t dst, const void* src) {
    asm volatile("cp.async.cg.shared.global [%0], [%1], 16;"
                 :: "r"(dst), "l"(src) : "memory");
}
#define CP_COMMIT() asm volatile("cp.async.commit_group;" ::: "memory")
#define CP_WAIT(n)  asm volatile("cp.async.wait_group %0;" :: "n"(n) : "memory")

// fp16 split
__device__ __forceinline__ void split2h(float x, float y, uint32_t& hi, uint32_t& lo) {
    __half hx = __float2half_rn(x);
    __half hy = __float2half_rn(y);
    __half lx = __float2half_rn(x - __half2float(hx));
    __half ly = __float2half_rn(y - __half2float(hy));
    hi = (uint32_t)__half_as_ushort(hx) | ((uint32_t)__half_as_ushort(hy) << 16);
    lo = (uint32_t)__half_as_ushort(lx) | ((uint32_t)__half_as_ushort(ly) << 16);
}

// swizzled byte offset in a [rows x 32 elems] 16-bit tile (64B rows, 4x16B units)
__device__ __forceinline__ uint32_t swz(int row, int c) {
    return (uint32_t)(row * 64 + ((c ^ ((row >> 1) & 3)) << 4));
}
// swizzled byte offset in a [rows x 128 elems] 16-bit tile (256B rows, 16x16B units)
__device__ __forceinline__ uint32_t swz256(int row, int c) {
    return (uint32_t)(row * 256 + ((c ^ (row & 7)) << 4));
}

// ---------------------------------------------------------------------------
// elementwise converters
// ---------------------------------------------------------------------------
__global__ void split_f32h(const float* __restrict__ x,
                           __half* __restrict__ hi, __half* __restrict__ lo)
{
    size_t i = ((size_t)blockIdx.x * blockDim.x + threadIdx.x) * 4;
    float4 f = *(const float4*)(x + i);
    uint2 h, l;
    split2h(f.x, f.y, h.x, l.x);
    split2h(f.z, f.w, h.y, l.y);
    *(uint2*)(hi + i) = h;
    *(uint2*)(lo + i) = l;
}
__global__ void conv_f32h(const float* __restrict__ x, __half* __restrict__ hi)
{
    size_t i = ((size_t)blockIdx.x * blockDim.x + threadIdx.x) * 4;
    float4 f = *(const float4*)(x + i);
    uint2 h;
    h.x = (uint32_t)__half_as_ushort(__float2half_rn(f.x))
        | ((uint32_t)__half_as_ushort(__float2half_rn(f.y)) << 16);
    h.y = (uint32_t)__half_as_ushort(__float2half_rn(f.z))
        | ((uint32_t)__half_as_ushort(__float2half_rn(f.w)) << 16);
    *(uint2*)(hi + i) = h;
}

// ---------------------------------------------------------------------------
// Fused pre-attention kernel: grid (M, NH+NKV+NKV).
//   blockIdx.y <  NH          : Q rmsnorm+rope -> fp16 hi/lo (prescaled)
//   blockIdx.y in [NH, NH+NKV): K rmsnorm+rope -> fp16 hi
//   blockIdx.y >= NH+NKV      : V -> fp16 hi
// ---------------------------------------------------------------------------
__global__ void norm_split(const float* __restrict__ qkv,
                           const float* __restrict__ qn, const float* __restrict__ kn,
                           __half* __restrict__ qhi, __half* __restrict__ qlo,
                           __half* __restrict__ kh, __half* __restrict__ vh)
{
    const int row = blockIdx.x;
    const int hb  = blockIdx.y;
    const int d   = threadIdx.x;
    const int s   = row & (SS - 1);

    if (hb >= NH + NKV) {
        const int h = hb - NH - NKV;
        float f = qkv[(size_t)row * NQKV + 2560 + h * HD + d];
        vh[((size_t)row * NKV + h) * HD + d] = __float2half_rn(f);
        return;
    }

    const bool isQ = (hb < NH);
    const int h = isQ ? hb : hb - NH;
    const int coloff = isQ ? 0 : 2048;
    const float* w = isQ ? qn : kn;
    const float prescale = isQ ? 0.08838834764831845f : 1.0f;

    float val = qkv[(size_t)row * NQKV + coloff + h * HD + d];

    float ss = val * val;
#pragma unroll
    for (int off = 16; off > 0; off >>= 1)
        ss += __shfl_xor_sync(0xffffffffu, ss, off);

    __shared__ float red[4];
    __shared__ float xs[128];
    const int warp = d >> 5, lane = d & 31;
    if (lane == 0) red[warp] = ss;
    __syncthreads();
    float tot = red[0] + red[1] + red[2] + red[3];
    float xn  = val * rsqrtf(tot * (1.0f / 128.0f) + 1e-5f) * w[d];
    xs[d] = xn;
    __syncthreads();

    const int i = d & 63;
    float inv_freq = expf(-(float)i * (13.122363377404328f / 64.0f));
    float ang = (float)s * inv_freq;
    float sn, cs;
    sincosf(ang, &sn, &cs);

    float other = xs[d ^ 64];
    float res = (d < 64) ? (xn * cs - other * sn) : (xn * cs + other * sn);
    res *= prescale;

    __half hv = __float2half_rn(res);
    if (isQ) {
        const size_t obase = ((size_t)row * NH + h) * HD;
        qhi[obase + d] = hv;
        qlo[obase + d] = __float2half_rn(res - __half2float(hv));
    } else {
        kh[((size_t)row * NKV + h) * HD + d] = hv;
    }
}

// ---------------------------------------------------------------------------
// fp16 2-pass split GEMM: C[M][N] = (Ahi+Alo)[M][K] * Bhi[N][K]^T (fp32 out)
// BM=BN=128, BK=32, 512 threads (16 warps 4x4), warp tile 32x32.
// 4-stage cp.async pipeline, ONE sync per chunk.
// ---------------------------------------------------------------------------
#define GS_AH 0
#define GS_AL 8192
#define GS_BH 16384
#define GS_STAGE 24576
#define GS_SMEM (4 * GS_STAGE)

__global__ void __launch_bounds__(512) gemm_fp16(
    const __half* __restrict__ Ahi, const __half* __restrict__ Alo,
    const __half* __restrict__ Bhi,
    float* __restrict__ C, int M, int N, int K)
{
    extern __shared__ char smem[];
    const uint32_t sb = smem_to_u32(smem);

    const int t = threadIdx.x;
    const int lane = t & 31, wid = t >> 5;
    const int bm = blockIdx.y * 128, bn = blockIdx.x * 128;
    const int wm = (wid & 3) * 32;
    const int wn = (wid >> 2) * 32;

    const int lrow = t >> 2, lc = t & 3;
    const size_t ga = (size_t)(bm + lrow) * K + lc * 8;
    const size_t gb = (size_t)(bn + lrow) * K + lc * 8;
    const uint32_t st = swz(lrow, lc);
    const int nch = K >> 5;

    auto issue = [&](int ch) {
        uint32_t base = sb + (uint32_t)(ch & 3) * GS_STAGE + st;
        size_t ka = ga + (size_t)ch * 32;
        size_t kb = gb + (size_t)ch * 32;
        cp_async16(base + GS_AH, Ahi + ka);
        cp_async16(base + GS_AL, Alo + ka);
        cp_async16(base + GS_BH, Bhi + kb);
    };

    issue(0); CP_COMMIT();
    issue(1); CP_COMMIT();
    issue(2); CP_COMMIT();

    float acc[2][4][4];
#pragma unroll
    for (int i = 0; i < 2; i++)
#pragma unroll
        for (int j = 0; j < 4; j++)
#pragma unroll
            for (int q = 0; q < 4; q++) acc[i][j][q] = 0.0f;

    for (int ch = 0; ch < nch; ch++) {
        CP_WAIT(2);
        __syncthreads();
        if (ch + 3 < nch) { issue(ch + 3); CP_COMMIT(); }

        const uint32_t base = sb + (uint32_t)(ch & 3) * GS_STAGE;
#pragma unroll
        for (int ks = 0; ks < 2; ks++) {
            uint32_t ah[2][4], al[2][4];
#pragma unroll
            for (int mt = 0; mt < 2; mt++) {
                int row = wm + mt * 16 + (lane & 15);
                int c = ks * 2 + (lane >> 4);
                uint32_t off = swz(row, c);
                ldsm_x4(ah[mt], base + GS_AH + off);
                ldsm_x4(al[mt], base + GS_AL + off);
            }
#pragma unroll
            for (int np = 0; np < 2; np++) {
                uint32_t bh[4];
                int row = wn + np * 16 + (lane & 7) + ((lane >> 4) & 1) * 8;
                int c = ks * 2 + ((lane >> 3) & 1);
                uint32_t off = swz(row, c);
                ldsm_x4(bh, base + GS_BH + off);
#pragma unroll
                for (int half = 0; half < 2; half++) {
                    int nt = np * 2 + half, pb = half * 2;
#pragma unroll
                    for (int mt = 0; mt < 2; mt++) {
                        mma16816h(acc[mt][nt], ah[mt], bh[pb], bh[pb + 1]);
                        mma16816h(acc[mt][nt], al[mt], bh[pb], bh[pb + 1]);
                    }
                }
            }
        }
    }

#pragma unroll
    for (int mt = 0; mt < 2; mt++)
#pragma unroll
        for (int nt = 0; nt < 4; nt++) {
            int r0 = bm + wm + mt * 16 + (lane >> 2);
            int c0 = bn + wn + nt * 8 + (lane & 3) * 2;
            float2 v0 = make_float2(acc[mt][nt][0], acc[mt][nt][1]);
            float2 v1 = make_float2(acc[mt][nt][2], acc[mt][nt][3]);
            *(float2*)&C[(size_t)r0 * N + c0] = v0;
            *(float2*)&C[(size_t)(r0 + 8) * N + c0] = v1;
        }
}

// ---------------------------------------------------------------------------
// Tensor-core causal flash attention, GQA — all fp16 2-pass.
// QK^T: (Qhi+Qlo) x Khi. PV: (Phi+Plo) x Vhi.
// BM=128, BN=64, D=128. 256 threads = 8 warps; warp tile m16 x n64.
// K/V double-buffered via cp.async, one sync per iteration.
// ---------------------------------------------------------------------------
#define SQ_HI 0
#define SQ_LO 32768
#define KV_BASE 65536
#define ST_KH 0
#define ST_VH 16384
#define KV_STAGE 32768
#define FL_SMEM (KV_BASE + 2 * KV_STAGE)

__global__ void __launch_bounds__(256) flash_attn_tc(
    const __half* __restrict__ qhi, const __half* __restrict__ qlo,
    const __half* __restrict__ kh, const __half* __restrict__ vh,
    __half* __restrict__ ohi, __half* __restrict__ olo)
{
    extern __shared__ char smem[];
    const uint32_t sb = smem_to_u32(smem);
    const int t = threadIdx.x, lane = t & 31, wid = t >> 5;
    const int qb = gridDim.x - 1 - blockIdx.x;   // heavy blocks first
    const int h = blockIdx.y, b = blockIdx.z;
    const int kvh = h >> 2;
    const int warp_m = wid * 16;
    const int QSTR = NH * HD;
    const int KSTR = NKV * HD;

    const int cr = t >> 4, cc = t & 15;
    const __half* kh0 = kh + ((size_t)(b * SS)) * KSTR + kvh * HD;
    const __half* vh0 = vh + ((size_t)(b * SS)) * KSTR + kvh * HD;

    auto issue_kv = [&](int kb) {
        uint32_t stage = sb + KV_BASE + (uint32_t)(kb & 1) * KV_STAGE;
#pragma unroll
        for (int i = 0; i < 4; i++) {
            int r = cr + i * 16;
            size_t g = (size_t)(kb * 64 + r) * KSTR + cc * 8;
            uint32_t s = swz256(r, cc);
            cp_async16(stage + ST_KH + s, kh0 + g);
            cp_async16(stage + ST_VH + s, vh0 + g);
        }
    };

    issue_kv(0); CP_COMMIT();

    {
        const __half* qh = qhi + ((size_t)(b * SS + qb * 128)) * QSTR + h * HD;
        const __half* ql = qlo + ((size_t)(b * SS + qb * 128)) * QSTR + h * HD;
#pragma unroll
        for (int i = 0; i < 8; i++) {
            int u = t + i * 256;
            int r = u >> 4, c = u & 15;
            size_t g = (size_t)r * QSTR + c * 8;
            uint32_t s = swz256(r, c);
            *(uint4*)(smem + SQ_HI + s) = *(const uint4*)(qh + g);
            *(uint4*)(smem + SQ_LO + s) = *(const uint4*)(ql + g);
        }
    }

    float m0 = -INFINITY, m1 = -INFINITY, l0 = 0.0f, l1 = 0.0f;
    float oacc[16][4];
#pragma unroll
    for (int i = 0; i < 16; i++)
#pragma unroll
        for (int j = 0; j < 4; j++) oacc[i][j] = 0.0f;

    const int row_lo = qb * 128 + warp_m + (lane >> 2);
    const int nkb = 2 * qb + 2;

    for (int kb = 0; kb < nkb; kb++) {
        CP_WAIT(0);
        __syncthreads();
        if (kb + 1 < nkb) { issue_kv(kb + 1); CP_COMMIT(); }

        if (kb * 64 > qb * 128 + warp_m + 15) continue;
        const bool need_mask = (kb * 64 + 63 > qb * 128 + warp_m);
        const uint32_t stage = sb + KV_BASE + (uint32_t)(kb & 1) * KV_STAGE;

        float sacc[8][4];
#pragma unroll
        for (int i = 0; i < 8; i++)
#pragma unroll
            for (int j = 0; j < 4; j++) sacc[i][j] = 0.0f;

#pragma unroll
        for (int ks = 0; ks < 8; ks++) {
            uint32_t ah[4], al[4];
            {
                int ar = warp_m + (lane & 15);
                int ac = ks * 2 + (lane >> 4);
                uint32_t off = swz256(ar, ac);
                ldsm_x4(ah, sb + SQ_HI + off);
                ldsm_x4(al, sb + SQ_LO + off);
            }
#pragma unroll
            for (int np = 0; np < 4; np++) {
                uint32_t bh[4];
                int br = np * 16 + (lane & 7) + ((lane >> 4) & 1) * 8;
                int bc = ks * 2 + ((lane >> 3) & 1);
                uint32_t off = swz256(br, bc);
                ldsm_x4(bh, stage + ST_KH + off);
#pragma unroll
                for (int half = 0; half < 2; half++) {
                    int nt = np * 2 + half, pb = half * 2;
                    mma16816h(sacc[nt], ah, bh[pb], bh[pb + 1]);
                    mma16816h(sacc[nt], al, bh[pb], bh[pb + 1]);
                }
            }
        }

        if (need_mask) {
#pragma unroll
            for (int nt = 0; nt < 8; nt++) {
                int col = kb * 64 + nt * 8 + (lane & 3) * 2;
#pragma unroll
                for (int j = 0; j < 4; j++) {
                    int cc2 = col + (j & 1);
                    int rr = row_lo + ((j >> 1) << 3);
                    if (cc2 > rr) sacc[nt][j] = -INFINITY;
                }
            }
        }

        float mt0 = -INFINITY, mt1 = -INFINITY;
#pragma unroll
        for (int nt = 0; nt < 8; nt++) {
            mt0 = fmaxf(mt0, fmaxf(sacc[nt][0], sacc[nt][1]));
            mt1 = fmaxf(mt1, fmaxf(sacc[nt][2], sacc[nt][3]));
        }
        mt0 = fmaxf(mt0, __shfl_xor_sync(0xffffffffu, mt0, 1));
        mt0 = fmaxf(mt0, __shfl_xor_sync(0xffffffffu, mt0, 2));
        mt1 = fmaxf(mt1, __shfl_xor_sync(0xffffffffu, mt1, 1));
        mt1 = fmaxf(mt1, __shfl_xor_sync(0xffffffffu, mt1, 2));

        float mn0 = fmaxf(m0, mt0), mn1 = fmaxf(m1, mt1);
        float sc0 = __expf(m0 - mn0), sc1 = __expf(m1 - mn1);
        m0 = mn0; m1 = mn1;

        float ps0 = 0.0f, ps1 = 0.0f;
#pragma unroll
        for (int nt = 0; nt < 8; nt++) {
            sacc[nt][0] = __expf(sacc[nt][0] - mn0);
            sacc[nt][1] = __expf(sacc[nt][1] - mn0);
            sacc[nt][2] = __expf(sacc[nt][2] - mn1);
            sacc[nt][3] = __expf(sacc[nt][3] - mn1);
            ps0 += sacc[nt][0] + sacc[nt][1];
            ps1 += sacc[nt][2] + sacc[nt][3];
        }
        ps0 += __shfl_xor_sync(0xffffffffu, ps0, 1);
        ps0 += __shfl_xor_sync(0xffffffffu, ps0, 2);
        ps1 += __shfl_xor_sync(0xffffffffu, ps1, 1);
        ps1 += __shfl_xor_sync(0xffffffffu, ps1, 2);
        l0 = l0 * sc0 + ps0;
        l1 = l1 * sc1 + ps1;

#pragma unroll
        for (int nt = 0; nt < 16; nt++) {
            oacc[nt][0] *= sc0; oacc[nt][1] *= sc0;
            oacc[nt][2] *= sc1; oacc[nt][3] *= sc1;
        }

        // ---- PV: fp16 2-pass (P hi+lo x V hi) ----
#pragma unroll
        for (int ks = 0; ks < 4; ks++) {
            uint32_t phi[4], plo[4];
            split2h(sacc[2 * ks][0], sacc[2 * ks][1], phi[0], plo[0]);
            split2h(sacc[2 * ks][2], sacc[2 * ks][3], phi[1], plo[1]);
            split2h(sacc[2 * ks + 1][0], sacc[2 * ks + 1][1], phi[2], plo[2]);
            split2h(sacc[2 * ks + 1][2], sacc[2 * ks + 1][3], phi[3], plo[3]);
#pragma unroll
            for (int dp = 0; dp < 8; dp++) {
                uint32_t vh4[4];
                int vr = ks * 16 + (lane & 7) + ((lane >> 3) & 1) * 8;
                int vc = dp * 2 + (lane >> 4);
                uint32_t off = swz256(vr, vc);
                ldsm_x4_t(vh4, stage + ST_VH + off);
                mma16816h(oacc[dp * 2], phi, vh4[0], vh4[1]);
                mma16816h(oacc[dp * 2], plo, vh4[0], vh4[1]);
                mma16816h(oacc[dp * 2 + 1], phi, vh4[2], vh4[3]);
                mma16816h(oacc[dp * 2 + 1], plo, vh4[2], vh4[3]);
            }
        }
    }

    // ---- epilogue: write fp16 hi/lo ----
    float il0 = 1.0f / l0, il1 = 1.0f / l1;
    __half* oh = ohi + ((size_t)(b * SS)) * QSTR + h * HD;
    __half* ol = olo + ((size_t)(b * SS)) * QSTR + h * HD;
    int r0 = qb * 128 + warp_m + (lane >> 2);
#pragma unroll
    for (int nt = 0; nt < 16; nt++) {
        int dim = nt * 8 + (lane & 3) * 2;
        uint32_t h0, l0b, h1, l1b;
        split2h(oacc[nt][0] * il0, oacc[nt][1] * il0, h0, l0b);
        split2h(oacc[nt][2] * il1, oacc[nt][3] * il1, h1, l1b);
        *(uint32_t*)&oh[(size_t)r0 * QSTR + dim] = h0;
        *(uint32_t*)&ol[(size_t)r0 * QSTR + dim] = l0b;
        *(uint32_t*)&oh[(size_t)(r0 + 8) * QSTR + dim] = h1;
        *(uint32_t*)&ol[(size_t)(r0 + 8) * QSTR + dim] = l1b;
    }
}

// ---------------------------------------------------------------------------
extern "C" void kernel_launch(void* const* d_in, const int* in_sizes, int n_in,
                              void* d_out, int out_size)
{
    const float* hs  = (const float*)d_in[0];
    const float* q_w = (const float*)d_in[1];
    const float* k_w = (const float*)d_in[2];
    const float* v_w = (const float*)d_in[3];
    const float* o_w = (const float*)d_in[4];
    const float* qn  = (const float*)d_in[5];
    const float* kn  = (const float*)d_in[6];
    float* out = (float*)d_out;

    float* pqkv;
    __half *hsh, *hsl, *qkvw, *owh, *pah, *pal, *pqh, *pql, *pkh, *pvh;
    cudaGetSymbolAddress((void**)&pqkv, g_qkv);
    cudaGetSymbolAddress((void**)&hsh, g_hs_hi);
    cudaGetSymbolAddress((void**)&hsl, g_hs_lo);
    cudaGetSymbolAddress((void**)&qkvw, g_qkvw_hi);
    cudaGetSymbolAddress((void**)&owh, g_ow_hi);
    cudaGetSymbolAddress((void**)&pah, g_ahi);
    cudaGetSymbolAddress((void**)&pal, g_alo);
    cudaGetSymbolAddress((void**)&pqh, g_qhi);
    cudaGetSymbolAddress((void**)&pql, g_qlo);
    cudaGetSymbolAddress((void**)&pkh, g_kh);
    cudaGetSymbolAddress((void**)&pvh, g_vh);

    const int M = BB * SS;     // 4096
    const int K = HH;          // 2048

    // operand conversion: A hi+lo fp16; fused QKV weight hi-only fp16
    split_f32h<<<(M * HH) / 1024, 256>>>(hs, hsh, hsl);
    conv_f32h<<<(NH * HD * HH) / 1024, 256>>>(q_w, qkvw);
    conv_f32h<<<(NKV * HD * HH) / 1024, 256>>>(k_w, qkvw + (size_t)2048 * HH);
    conv_f32h<<<(NKV * HD * HH) / 1024, 256>>>(v_w, qkvw + (size_t)2560 * HH);
    conv_f32h<<<(HH * NH * HD) / 1024, 256>>>(o_w, owh);

    cudaFuncSetAttribute(gemm_fp16, cudaFuncAttributeMaxDynamicSharedMemorySize,
                         GS_SMEM);

    // fused QKV projection: one GEMM, N = 3072
    gemm_fp16<<<dim3(NQKV / 128, M / 128), 512, GS_SMEM>>>(hsh, hsl, qkvw,
                                                           pqkv, M, NQKV, K);

    // fused rmsnorm+rope (Q fp16 hi/lo, K fp16 hi) + V convert: one launch
    norm_split<<<dim3(M, NH + NKV + NKV), 128>>>(pqkv, qn, kn,
                                                 pqh, pql, pkh, pvh);

    // tensor-core causal flash attention (fp16 2-pass QK and PV)
    cudaFuncSetAttribute(flash_attn_tc, cudaFuncAttributeMaxDynamicSharedMemorySize,
                         FL_SMEM);
    flash_attn_tc<<<dim3(SS / 128, NH, BB), 256, FL_SMEM>>>(pqh, pql, pkh, pvh,
                                                            pah, pal);

    // output projection (fp16 2-pass)
    gemm_fp16<<<dim3(HH / 128, M / 128), 512, GS_SMEM>>>(pah, pal, owh,
                                                         out, M, HH, K);
}

// round 12
// speedup vs baseline: 1.1824x; 1.0650x over previous
#include <cuda_runtime.h>
#include <cuda_bf16.h>
#include <cuda_fp16.h>
#include <stdint.h>
#include <math.h>

#define BB 2
#define SS 2048
#define HH 2048
#define NH 16
#define NKV 4
#define HD 128
#define NQKV 3072   // fused QKV output width: 2048 + 512 + 512

// ---------------- scratch (device globals: allocation-free) ----------------
__device__ float g_qkv[(size_t)BB * SS * NQKV];      // fused QKV projection out
// fp16 split GEMM operands (A side: hi+lo; B side: hi only)
__device__ __half g_hs_hi[(size_t)BB * SS * HH];
__device__ __half g_hs_lo[(size_t)BB * SS * HH];
__device__ __half g_qkvw_hi[(size_t)NQKV * HH];      // fused QKV weights
__device__ __half g_ow_hi[(size_t)HH * NH * HD];
// post-norm attention operands: Q fp16 hi/lo, K fp16 hi, V fp16 hi
__device__ __half g_qhi[(size_t)BB * SS * NH * HD];
__device__ __half g_qlo[(size_t)BB * SS * NH * HD];
__device__ __half g_kh[(size_t)BB * SS * NKV * HD];
__device__ __half g_vh[(size_t)BB * SS * NKV * HD];
// attention output (fp16 hi/lo, feeds O projection)
__device__ __half g_ahi[(size_t)BB * SS * NH * HD];
__device__ __half g_alo[(size_t)BB * SS * NH * HD];

// ===================== warp-MMA helpers =====================
__device__ __forceinline__ uint32_t smem_to_u32(const void* p) {
    uint32_t a;
    asm("{ .reg .u64 t; cvta.to.shared.u64 t, %1; cvt.u32.u64 %0, t; }"
        : "=r"(a) : "l"(p));
    return a;
}
__device__ __forceinline__ void ldsm_x4(uint32_t r[4], uint32_t addr) {
    asm volatile("ldmatrix.sync.aligned.m8n8.x4.shared.b16 {%0,%1,%2,%3}, [%4];"
                 : "=r"(r[0]), "=r"(r[1]), "=r"(r[2]), "=r"(r[3]) : "r"(addr));
}
__device__ __forceinline__ void ldsm_x4_t(uint32_t r[4], uint32_t addr) {
    asm volatile("ldmatrix.sync.aligned.m8n8.x4.trans.shared.b16 {%0,%1,%2,%3}, [%4];"
                 : "=r"(r[0]), "=r"(r[1]), "=r"(r[2]), "=r"(r[3]) : "r"(addr));
}
// fp16 MMA
__device__ __forceinline__ void mma16816h(float c[4], const uint32_t a[4],
                                          const uint32_t b0, const uint32_t b1) {
    asm volatile(
        "mma.sync.aligned.m16n8k16.row.col.f32.f16.f16.f32 "
        "{%0,%1,%2,%3}, {%4,%5,%6,%7}, {%8,%9}, {%0,%1,%2,%3};"
        : "+f"(c[0]), "+f"(c[1]), "+f"(c[2]), "+f"(c[3])
        : "r"(a[0]), "r"(a[1]), "r"(a[2]), "r"(a[3]), "r"(b0), "r"(b1));
}
__device__ __forceinline__ void cp_async16(uint32_t dst, const void* src) {
    asm volatile("cp.async.cg.shared.global [%0], [%1], 16;"
                 :: "r"(dst), "l"(src) : "memory");
}
#define CP_COMMIT() asm volatile("cp.async.commit_group;" ::: "memory")
#define CP_WAIT(n)  asm volatile("cp.async.wait_group %0;" :: "n"(n) : "memory")

// fp16 split / pack
__device__ __forceinline__ void split2h(float x, float y, uint32_t& hi, uint32_t& lo) {
    __half hx = __float2half_rn(x);
    __half hy = __float2half_rn(y);
    __half lx = __float2half_rn(x - __half2float(hx));
    __half ly = __float2half_rn(y - __half2float(hy));
    hi = (uint32_t)__half_as_ushort(hx) | ((uint32_t)__half_as_ushort(hy) << 16);
    lo = (uint32_t)__half_as_ushort(lx) | ((uint32_t)__half_as_ushort(ly) << 16);
}
__device__ __forceinline__ uint32_t pack2h(float x, float y) {
    return (uint32_t)__half_as_ushort(__float2half_rn(x))
         | ((uint32_t)__half_as_ushort(__float2half_rn(y)) << 16);
}

// swizzled byte offset in a [rows x 32 elems] 16-bit tile (64B rows, 4x16B units)
__device__ __forceinline__ uint32_t swz(int row, int c) {
    return (uint32_t)(row * 64 + ((c ^ ((row >> 1) & 3)) << 4));
}
// swizzled byte offset in a [rows x 128 elems] 16-bit tile (256B rows, 16x16B units)
__device__ __forceinline__ uint32_t swz256(int row, int c) {
    return (uint32_t)(row * 256 + ((c ^ (row & 7)) << 4));
}

// ---------------------------------------------------------------------------
// fused converter: one launch handles hs split + all 4 weight converts.
// block regions (each block = 256 thr x 4 elems = 1024 elems):
//   [0, 8192)          : hs split -> hi+lo
//   [8192, 12288)      : q_w -> qkvw[0]
//   [12288, 13312)     : k_w -> qkvw + 2048*HH
//   [13312, 14336)     : v_w -> qkvw + 2560*HH
//   [14336, 18432)     : o_w -> owh
// ---------------------------------------------------------------------------
__global__ void conv_all(const float* __restrict__ hs,
                         const float* __restrict__ qw, const float* __restrict__ kw,
                         const float* __restrict__ vw, const float* __restrict__ ow,
                         __half* __restrict__ hsh, __half* __restrict__ hsl,
                         __half* __restrict__ qkvw, __half* __restrict__ owh)
{
    const int blk = blockIdx.x;
    if (blk < 8192) {
        size_t i = ((size_t)blk * 256 + threadIdx.x) * 4;
        float4 f = *(const float4*)(hs + i);
        uint2 h, l;
        split2h(f.x, f.y, h.x, l.x);
        split2h(f.z, f.w, h.y, l.y);
        *(uint2*)(hsh + i) = h;
        *(uint2*)(hsl + i) = l;
        return;
    }
    const float* src;
    __half* dst;
    int base;
    if (blk < 12288)      { src = qw; dst = qkvw;                      base = blk - 8192; }
    else if (blk < 13312) { src = kw; dst = qkvw + (size_t)2048 * HH;  base = blk - 12288; }
    else if (blk < 14336) { src = vw; dst = qkvw + (size_t)2560 * HH;  base = blk - 13312; }
    else                  { src = ow; dst = owh;                       base = blk - 14336; }
    size_t i = ((size_t)base * 256 + threadIdx.x) * 4;
    float4 f = *(const float4*)(src + i);
    uint2 h;
    h.x = pack2h(f.x, f.y);
    h.y = pack2h(f.z, f.w);
    *(uint2*)(dst + i) = h;
}

// ---------------------------------------------------------------------------
// Fused pre-attention kernel: grid (M, NH+NKV+NKV).
// ---------------------------------------------------------------------------
__global__ void norm_split(const float* __restrict__ qkv,
                           const float* __restrict__ qn, const float* __restrict__ kn,
                           __half* __restrict__ qhi, __half* __restrict__ qlo,
                           __half* __restrict__ kh, __half* __restrict__ vh)
{
    const int row = blockIdx.x;
    const int hb  = blockIdx.y;
    const int d   = threadIdx.x;
    const int s   = row & (SS - 1);

    if (hb >= NH + NKV) {
        const int h = hb - NH - NKV;
        float f = qkv[(size_t)row * NQKV + 2560 + h * HD + d];
        vh[((size_t)row * NKV + h) * HD + d] = __float2half_rn(f);
        return;
    }

    const bool isQ = (hb < NH);
    const int h = isQ ? hb : hb - NH;
    const int coloff = isQ ? 0 : 2048;
    const float* w = isQ ? qn : kn;
    const float prescale = isQ ? 0.08838834764831845f : 1.0f;

    float val = qkv[(size_t)row * NQKV + coloff + h * HD + d];

    float ss = val * val;
#pragma unroll
    for (int off = 16; off > 0; off >>= 1)
        ss += __shfl_xor_sync(0xffffffffu, ss, off);

    __shared__ float red[4];
    __shared__ float xs[128];
    const int warp = d >> 5, lane = d & 31;
    if (lane == 0) red[warp] = ss;
    __syncthreads();
    float tot = red[0] + red[1] + red[2] + red[3];
    float xn  = val * rsqrtf(tot * (1.0f / 128.0f) + 1e-5f) * w[d];
    xs[d] = xn;
    __syncthreads();

    const int i = d & 63;
    float inv_freq = expf(-(float)i * (13.122363377404328f / 64.0f));
    float ang = (float)s * inv_freq;
    float sn, cs;
    sincosf(ang, &sn, &cs);

    float other = xs[d ^ 64];
    float res = (d < 64) ? (xn * cs - other * sn) : (xn * cs + other * sn);
    res *= prescale;

    __half hv = __float2half_rn(res);
    if (isQ) {
        const size_t obase = ((size_t)row * NH + h) * HD;
        qhi[obase + d] = hv;
        qlo[obase + d] = __float2half_rn(res - __half2float(hv));
    } else {
        kh[((size_t)row * NKV + h) * HD + d] = hv;
    }
}

// ---------------------------------------------------------------------------
// fp16 2-pass split GEMM: C[M][N] = (Ahi+Alo)[M][K] * Bhi[N][K]^T (fp32 out)
// ---------------------------------------------------------------------------
#define GS_AH 0
#define GS_AL 8192
#define GS_BH 16384
#define GS_STAGE 24576
#define GS_SMEM (4 * GS_STAGE)

__global__ void __launch_bounds__(512) gemm_fp16(
    const __half* __restrict__ Ahi, const __half* __restrict__ Alo,
    const __half* __restrict__ Bhi,
    float* __restrict__ C, int M, int N, int K)
{
    extern __shared__ char smem[];
    const uint32_t sb = smem_to_u32(smem);

    const int t = threadIdx.x;
    const int lane = t & 31, wid = t >> 5;
    const int bm = blockIdx.y * 128, bn = blockIdx.x * 128;
    const int wm = (wid & 3) * 32;
    const int wn = (wid >> 2) * 32;

    const int lrow = t >> 2, lc = t & 3;
    const size_t ga = (size_t)(bm + lrow) * K + lc * 8;
    const size_t gb = (size_t)(bn + lrow) * K + lc * 8;
    const uint32_t st = swz(lrow, lc);
    const int nch = K >> 5;

    auto issue = [&](int ch) {
        uint32_t base = sb + (uint32_t)(ch & 3) * GS_STAGE + st;
        size_t ka = ga + (size_t)ch * 32;
        size_t kb = gb + (size_t)ch * 32;
        cp_async16(base + GS_AH, Ahi + ka);
        cp_async16(base + GS_AL, Alo + ka);
        cp_async16(base + GS_BH, Bhi + kb);
    };

    issue(0); CP_COMMIT();
    issue(1); CP_COMMIT();
    issue(2); CP_COMMIT();

    float acc[2][4][4];
#pragma unroll
    for (int i = 0; i < 2; i++)
#pragma unroll
        for (int j = 0; j < 4; j++)
#pragma unroll
            for (int q = 0; q < 4; q++) acc[i][j][q] = 0.0f;

    for (int ch = 0; ch < nch; ch++) {
        CP_WAIT(2);
        __syncthreads();
        if (ch + 3 < nch) { issue(ch + 3); CP_COMMIT(); }

        const uint32_t base = sb + (uint32_t)(ch & 3) * GS_STAGE;
#pragma unroll
        for (int ks = 0; ks < 2; ks++) {
            uint32_t ah[2][4], al[2][4];
#pragma unroll
            for (int mt = 0; mt < 2; mt++) {
                int row = wm + mt * 16 + (lane & 15);
                int c = ks * 2 + (lane >> 4);
                uint32_t off = swz(row, c);
                ldsm_x4(ah[mt], base + GS_AH + off);
                ldsm_x4(al[mt], base + GS_AL + off);
            }
#pragma unroll
            for (int np = 0; np < 2; np++) {
                uint32_t bh[4];
                int row = wn + np * 16 + (lane & 7) + ((lane >> 4) & 1) * 8;
                int c = ks * 2 + ((lane >> 3) & 1);
                uint32_t off = swz(row, c);
                ldsm_x4(bh, base + GS_BH + off);
#pragma unroll
                for (int half = 0; half < 2; half++) {
                    int nt = np * 2 + half, pb = half * 2;
#pragma unroll
                    for (int mt = 0; mt < 2; mt++) {
                        mma16816h(acc[mt][nt], ah[mt], bh[pb], bh[pb + 1]);
                        mma16816h(acc[mt][nt], al[mt], bh[pb], bh[pb + 1]);
                    }
                }
            }
        }
    }

#pragma unroll
    for (int mt = 0; mt < 2; mt++)
#pragma unroll
        for (int nt = 0; nt < 4; nt++) {
            int r0 = bm + wm + mt * 16 + (lane >> 2);
            int c0 = bn + wn + nt * 8 + (lane & 3) * 2;
            float2 v0 = make_float2(acc[mt][nt][0], acc[mt][nt][1]);
            float2 v1 = make_float2(acc[mt][nt][2], acc[mt][nt][3]);
            *(float2*)&C[(size_t)r0 * N + c0] = v0;
            *(float2*)&C[(size_t)(r0 + 8) * N + c0] = v1;
        }
}

// ---------------------------------------------------------------------------
// Tensor-core causal flash attention, GQA.
// QK^T: fp16 2-pass (Qhi+Qlo x Khi). PV: fp16 1-pass (Phi x Vhi).
// BM=128, BN=64, D=128. 256 threads = 8 warps; warp tile m16 x n64.
// ---------------------------------------------------------------------------
#define SQ_HI 0
#define SQ_LO 32768
#define KV_BASE 65536
#define ST_KH 0
#define ST_VH 16384
#define KV_STAGE 32768
#define FL_SMEM (KV_BASE + 2 * KV_STAGE)

__global__ void __launch_bounds__(256) flash_attn_tc(
    const __half* __restrict__ qhi, const __half* __restrict__ qlo,
    const __half* __restrict__ kh, const __half* __restrict__ vh,
    __half* __restrict__ ohi, __half* __restrict__ olo)
{
    extern __shared__ char smem[];
    const uint32_t sb = smem_to_u32(smem);
    const int t = threadIdx.x, lane = t & 31, wid = t >> 5;
    const int qb = gridDim.x - 1 - blockIdx.x;   // heavy blocks first
    const int h = blockIdx.y, b = blockIdx.z;
    const int kvh = h >> 2;
    const int warp_m = wid * 16;
    const int QSTR = NH * HD;
    const int KSTR = NKV * HD;

    const int cr = t >> 4, cc = t & 15;
    const __half* kh0 = kh + ((size_t)(b * SS)) * KSTR + kvh * HD;
    const __half* vh0 = vh + ((size_t)(b * SS)) * KSTR + kvh * HD;

    auto issue_kv = [&](int kb) {
        uint32_t stage = sb + KV_BASE + (uint32_t)(kb & 1) * KV_STAGE;
#pragma unroll
        for (int i = 0; i < 4; i++) {
            int r = cr + i * 16;
            size_t g = (size_t)(kb * 64 + r) * KSTR + cc * 8;
            uint32_t s = swz256(r, cc);
            cp_async16(stage + ST_KH + s, kh0 + g);
            cp_async16(stage + ST_VH + s, vh0 + g);
        }
    };

    issue_kv(0); CP_COMMIT();

    {
        const __half* qh = qhi + ((size_t)(b * SS + qb * 128)) * QSTR + h * HD;
        const __half* ql = qlo + ((size_t)(b * SS + qb * 128)) * QSTR + h * HD;
#pragma unroll
        for (int i = 0; i < 8; i++) {
            int u = t + i * 256;
            int r = u >> 4, c = u & 15;
            size_t g = (size_t)r * QSTR + c * 8;
            uint32_t s = swz256(r, c);
            *(uint4*)(smem + SQ_HI + s) = *(const uint4*)(qh + g);
            *(uint4*)(smem + SQ_LO + s) = *(const uint4*)(ql + g);
        }
    }

    float m0 = -INFINITY, m1 = -INFINITY, l0 = 0.0f, l1 = 0.0f;
    float oacc[16][4];
#pragma unroll
    for (int i = 0; i < 16; i++)
#pragma unroll
        for (int j = 0; j < 4; j++) oacc[i][j] = 0.0f;

    const int row_lo = qb * 128 + warp_m + (lane >> 2);
    const int nkb = 2 * qb + 2;

    for (int kb = 0; kb < nkb; kb++) {
        CP_WAIT(0);
        __syncthreads();
        if (kb + 1 < nkb) { issue_kv(kb + 1); CP_COMMIT(); }

        if (kb * 64 > qb * 128 + warp_m + 15) continue;
        const bool need_mask = (kb * 64 + 63 > qb * 128 + warp_m);
        const uint32_t stage = sb + KV_BASE + (uint32_t)(kb & 1) * KV_STAGE;

        float sacc[8][4];
#pragma unroll
        for (int i = 0; i < 8; i++)
#pragma unroll
            for (int j = 0; j < 4; j++) sacc[i][j] = 0.0f;

#pragma unroll
        for (int ks = 0; ks < 8; ks++) {
            uint32_t ah[4], al[4];
            {
                int ar = warp_m + (lane & 15);
                int ac = ks * 2 + (lane >> 4);
                uint32_t off = swz256(ar, ac);
                ldsm_x4(ah, sb + SQ_HI + off);
                ldsm_x4(al, sb + SQ_LO + off);
            }
#pragma unroll
            for (int np = 0; np < 4; np++) {
                uint32_t bh[4];
                int br = np * 16 + (lane & 7) + ((lane >> 4) & 1) * 8;
                int bc = ks * 2 + ((lane >> 3) & 1);
                uint32_t off = swz256(br, bc);
                ldsm_x4(bh, stage + ST_KH + off);
#pragma unroll
                for (int half = 0; half < 2; half++) {
                    int nt = np * 2 + half, pb = half * 2;
                    mma16816h(sacc[nt], ah, bh[pb], bh[pb + 1]);
                    mma16816h(sacc[nt], al, bh[pb], bh[pb + 1]);
                }
            }
        }

        if (need_mask) {
#pragma unroll
            for (int nt = 0; nt < 8; nt++) {
                int col = kb * 64 + nt * 8 + (lane & 3) * 2;
#pragma unroll
                for (int j = 0; j < 4; j++) {
                    int cc2 = col + (j & 1);
                    int rr = row_lo + ((j >> 1) << 3);
                    if (cc2 > rr) sacc[nt][j] = -INFINITY;
                }
            }
        }

        float mt0 = -INFINITY, mt1 = -INFINITY;
#pragma unroll
        for (int nt = 0; nt < 8; nt++) {
            mt0 = fmaxf(mt0, fmaxf(sacc[nt][0], sacc[nt][1]));
            mt1 = fmaxf(mt1, fmaxf(sacc[nt][2], sacc[nt][3]));
        }
        mt0 = fmaxf(mt0, __shfl_xor_sync(0xffffffffu, mt0, 1));
        mt0 = fmaxf(mt0, __shfl_xor_sync(0xffffffffu, mt0, 2));
        mt1 = fmaxf(mt1, __shfl_xor_sync(0xffffffffu, mt1, 1));
        mt1 = fmaxf(mt1, __shfl_xor_sync(0xffffffffu, mt1, 2));

        float mn0 = fmaxf(m0, mt0), mn1 = fmaxf(m1, mt1);
        float sc0 = __expf(m0 - mn0), sc1 = __expf(m1 - mn1);
        m0 = mn0; m1 = mn1;

        float ps0 = 0.0f, ps1 = 0.0f;
#pragma unroll
        for (int nt = 0; nt < 8; nt++) {
            sacc[nt][0] = __expf(sacc[nt][0] - mn0);
            sacc[nt][1] = __expf(sacc[nt][1] - mn0);
            sacc[nt][2] = __expf(sacc[nt][2] - mn1);
            sacc[nt][3] = __expf(sacc[nt][3] - mn1);
            ps0 += sacc[nt][0] + sacc[nt][1];
            ps1 += sacc[nt][2] + sacc[nt][3];
        }
        ps0 += __shfl_xor_sync(0xffffffffu, ps0, 1);
        ps0 += __shfl_xor_sync(0xffffffffu, ps0, 2);
        ps1 += __shfl_xor_sync(0xffffffffu, ps1, 1);
        ps1 += __shfl_xor_sync(0xffffffffu, ps1, 2);
        l0 = l0 * sc0 + ps0;
        l1 = l1 * sc1 + ps1;

#pragma unroll
        for (int nt = 0; nt < 16; nt++) {
            oacc[nt][0] *= sc0; oacc[nt][1] *= sc0;
            oacc[nt][2] *= sc1; oacc[nt][3] *= sc1;
        }

        // ---- PV: fp16 1-pass (P hi x V hi) ----
#pragma unroll
        for (int ks = 0; ks < 4; ks++) {
            uint32_t phi[4];
            phi[0] = pack2h(sacc[2 * ks][0], sacc[2 * ks][1]);
            phi[1] = pack2h(sacc[2 * ks][2], sacc[2 * ks][3]);
            phi[2] = pack2h(sacc[2 * ks + 1][0], sacc[2 * ks + 1][1]);
            phi[3] = pack2h(sacc[2 * ks + 1][2], sacc[2 * ks + 1][3]);
#pragma unroll
            for (int dp = 0; dp < 8; dp++) {
                uint32_t vh4[4];
                int vr = ks * 16 + (lane & 7) + ((lane >> 3) & 1) * 8;
                int vc = dp * 2 + (lane >> 4);
                uint32_t off = swz256(vr, vc);
                ldsm_x4_t(vh4, stage + ST_VH + off);
                mma16816h(oacc[dp * 2], phi, vh4[0], vh4[1]);
                mma16816h(oacc[dp * 2 + 1], phi, vh4[2], vh4[3]);
            }
        }
    }

    // ---- epilogue: write fp16 hi/lo ----
    float il0 = 1.0f / l0, il1 = 1.0f / l1;
    __half* oh = ohi + ((size_t)(b * SS)) * QSTR + h * HD;
    __half* ol = olo + ((size_t)(b * SS)) * QSTR + h * HD;
    int r0 = qb * 128 + warp_m + (lane >> 2);
#pragma unroll
    for (int nt = 0; nt < 16; nt++) {
        int dim = nt * 8 + (lane & 3) * 2;
        uint32_t h0, l0b, h1, l1b;
        split2h(oacc[nt][0] * il0, oacc[nt][1] * il0, h0, l0b);
        split2h(oacc[nt][2] * il1, oacc[nt][3] * il1, h1, l1b);
        *(uint32_t*)&oh[(size_t)r0 * QSTR + dim] = h0;
        *(uint32_t*)&ol[(size_t)r0 * QSTR + dim] = l0b;
        *(uint32_t*)&oh[(size_t)(r0 + 8) * QSTR + dim] = h1;
        *(uint32_t*)&ol[(size_t)(r0 + 8) * QSTR + dim] = l1b;
    }
}

// ---------------------------------------------------------------------------
extern "C" void kernel_launch(void* const* d_in, const int* in_sizes, int n_in,
                              void* d_out, int out_size)
{
    const float* hs  = (const float*)d_in[0];
    const float* q_w = (const float*)d_in[1];
    const float* k_w = (const float*)d_in[2];
    const float* v_w = (const float*)d_in[3];
    const float* o_w = (const float*)d_in[4];
    const float* qn  = (const float*)d_in[5];
    const float* kn  = (const float*)d_in[6];
    float* out = (float*)d_out;

    float* pqkv;
    __half *hsh, *hsl, *qkvw, *owh, *pah, *pal, *pqh, *pql, *pkh, *pvh;
    cudaGetSymbolAddress((void**)&pqkv, g_qkv);
    cudaGetSymbolAddress((void**)&hsh, g_hs_hi);
    cudaGetSymbolAddress((void**)&hsl, g_hs_lo);
    cudaGetSymbolAddress((void**)&qkvw, g_qkvw_hi);
    cudaGetSymbolAddress((void**)&owh, g_ow_hi);
    cudaGetSymbolAddress((void**)&pah, g_ahi);
    cudaGetSymbolAddress((void**)&pal, g_alo);
    cudaGetSymbolAddress((void**)&pqh, g_qhi);
    cudaGetSymbolAddress((void**)&pql, g_qlo);
    cudaGetSymbolAddress((void**)&pkh, g_kh);
    cudaGetSymbolAddress((void**)&pvh, g_vh);

    const int M = BB * SS;     // 4096
    const int K = HH;          // 2048

    // fused operand conversion (hs split + 4 weight converts), one launch
    conv_all<<<18432, 256>>>(hs, q_w, k_w, v_w, o_w, hsh, hsl, qkvw, owh);

    cudaFuncSetAttribute(gemm_fp16, cudaFuncAttributeMaxDynamicSharedMemorySize,
                         GS_SMEM);

    // fused QKV projection: one GEMM, N = 3072
    gemm_fp16<<<dim3(NQKV / 128, M / 128), 512, GS_SMEM>>>(hsh, hsl, qkvw,
                                                           pqkv, M, NQKV, K);

    // fused rmsnorm+rope (Q fp16 hi/lo, K fp16 hi) + V convert: one launch
    norm_split<<<dim3(M, NH + NKV + NKV), 128>>>(pqkv, qn, kn,
                                                 pqh, pql, pkh, pvh);

    // tensor-core causal flash attention (QK 2-pass, PV 1-pass fp16)
    cudaFuncSetAttribute(flash_attn_tc, cudaFuncAttributeMaxDynamicSharedMemorySize,
                         FL_SMEM);
    flash_attn_tc<<<dim3(SS / 128, NH, BB), 256, FL_SMEM>>>(pqh, pql, pkh, pvh,
                                                            pah, pal);

    // output projection (fp16 2-pass)
    gemm_fp16<<<dim3(HH / 128, M / 128), 512, GS_SMEM>>>(pah, pal, owh,
                                                         out, M, HH, K);
}

// round 13
// speedup vs baseline: 1.6287x; 1.3774x over previous
#include <cuda_runtime.h>
#include <cuda_bf16.h>
#include <cuda_fp16.h>
#include <stdint.h>
#include <math.h>

#define BB 2
#define SS 2048
#define HH 2048
#define NH 16
#define NKV 4
#define HD 128
#define NQKV 3072   // fused QKV output width: 2048 + 512 + 512

// ---------------- scratch (device globals: allocation-free) ----------------
__device__ float g_qkv[(size_t)BB * SS * NQKV];      // fused QKV projection out
// fp16 GEMM operands (1-pass: hi only both sides)
__device__ __half g_hs_hi[(size_t)BB * SS * HH];
__device__ __half g_qkvw_hi[(size_t)NQKV * HH];      // fused QKV weights
__device__ __half g_ow_hi[(size_t)HH * NH * HD];
// post-norm attention operands: Q fp16 hi/lo, K fp16 hi, V fp16 hi
__device__ __half g_qhi[(size_t)BB * SS * NH * HD];
__device__ __half g_qlo[(size_t)BB * SS * NH * HD];
__device__ __half g_kh[(size_t)BB * SS * NKV * HD];
__device__ __half g_vh[(size_t)BB * SS * NKV * HD];
// attention output (fp16 hi, feeds 1-pass O projection)
__device__ __half g_ahi[(size_t)BB * SS * NH * HD];

// ===================== warp-MMA helpers =====================
__device__ __forceinline__ uint32_t smem_to_u32(const void* p) {
    uint32_t a;
    asm("{ .reg .u64 t; cvta.to.shared.u64 t, %1; cvt.u32.u64 %0, t; }"
        : "=r"(a) : "l"(p));
    return a;
}
__device__ __forceinline__ void ldsm_x4(uint32_t r[4], uint32_t addr) {
    asm volatile("ldmatrix.sync.aligned.m8n8.x4.shared.b16 {%0,%1,%2,%3}, [%4];"
                 : "=r"(r[0]), "=r"(r[1]), "=r"(r[2]), "=r"(r[3]) : "r"(addr));
}
__device__ __forceinline__ void ldsm_x4_t(uint32_t r[4], uint32_t addr) {
    asm volatile("ldmatrix.sync.aligned.m8n8.x4.trans.shared.b16 {%0,%1,%2,%3}, [%4];"
                 : "=r"(r[0]), "=r"(r[1]), "=r"(r[2]), "=r"(r[3]) : "r"(addr));
}
// fp16 MMA
__device__ __forceinline__ void mma16816h(float c[4], const uint32_t a[4],
                                          const uint32_t b0, const uint32_t b1) {
    asm volatile(
        "mma.sync.aligned.m16n8k16.row.col.f32.f16.f16.f32 "
        "{%0,%1,%2,%3}, {%4,%5,%6,%7}, {%8,%9}, {%0,%1,%2,%3};"
        : "+f"(c[0]), "+f"(c[1]), "+f"(c[2]), "+f"(c[3])
        : "r"(a[0]), "r"(a[1]), "r"(a[2]), "r"(a[3]), "r"(b0), "r"(b1));
}
__device__ __forceinline__ void cp_async16(uint32_t dst, const void* src) {
    asm volatile("cp.async.cg.shared.global [%0], [%1], 16;"
                 :: "r"(dst), "l"(src) : "memory");
}
#define CP_COMMIT() asm volatile("cp.async.commit_group;" ::: "memory")
#define CP_WAIT(n)  asm volatile("cp.async.wait_group %0;" :: "n"(n) : "memory")

// fp16 pack / split
__device__ __forceinline__ uint32_t pack2h(float x, float y) {
    return (uint32_t)__half_as_ushort(__float2half_rn(x))
         | ((uint32_t)__half_as_ushort(__float2half_rn(y)) << 16);
}

// swizzled byte offset in a [rows x 32 elems] 16-bit tile (64B rows, 4x16B units)
__device__ __forceinline__ uint32_t swz(int row, int c) {
    return (uint32_t)(row * 64 + ((c ^ ((row >> 1) & 3)) << 4));
}
// swizzled byte offset in a [rows x 128 elems] 16-bit tile (256B rows, 16x16B units)
__device__ __forceinline__ uint32_t swz256(int row, int c) {
    return (uint32_t)(row * 256 + ((c ^ (row & 7)) << 4));
}

// ---------------------------------------------------------------------------
// fused converter: one launch, all 5 fp32->fp16 converts.
// block regions (each block = 256 thr x 4 elems = 1024 elems):
//   [0, 8192)          : hs -> hsh
//   [8192, 12288)      : q_w -> qkvw[0]
//   [12288, 13312)     : k_w -> qkvw + 2048*HH
//   [13312, 14336)     : v_w -> qkvw + 2560*HH
//   [14336, 18432)     : o_w -> owh
// ---------------------------------------------------------------------------
__global__ void conv_all(const float* __restrict__ hs,
                         const float* __restrict__ qw, const float* __restrict__ kw,
                         const float* __restrict__ vw, const float* __restrict__ ow,
                         __half* __restrict__ hsh,
                         __half* __restrict__ qkvw, __half* __restrict__ owh)
{
    const int blk = blockIdx.x;
    const float* src;
    __half* dst;
    int base;
    if (blk < 8192)       { src = hs; dst = hsh;                       base = blk; }
    else if (blk < 12288) { src = qw; dst = qkvw;                      base = blk - 8192; }
    else if (blk < 13312) { src = kw; dst = qkvw + (size_t)2048 * HH;  base = blk - 12288; }
    else if (blk < 14336) { src = vw; dst = qkvw + (size_t)2560 * HH;  base = blk - 13312; }
    else                  { src = ow; dst = owh;                       base = blk - 14336; }
    size_t i = ((size_t)base * 256 + threadIdx.x) * 4;
    float4 f = *(const float4*)(src + i);
    uint2 h;
    h.x = pack2h(f.x, f.y);
    h.y = pack2h(f.z, f.w);
    *(uint2*)(dst + i) = h;
}

// ---------------------------------------------------------------------------
// Fused pre-attention kernel: grid (M, NH+NKV+NKV).
//   blockIdx.y <  NH          : Q rmsnorm+rope -> fp16 hi/lo (prescaled)
//   blockIdx.y in [NH, NH+NKV): K rmsnorm+rope -> fp16 hi
//   blockIdx.y >= NH+NKV      : V -> fp16 hi
// ---------------------------------------------------------------------------
__global__ void norm_split(const float* __restrict__ qkv,
                           const float* __restrict__ qn, const float* __restrict__ kn,
                           __half* __restrict__ qhi, __half* __restrict__ qlo,
                           __half* __restrict__ kh, __half* __restrict__ vh)
{
    const int row = blockIdx.x;
    const int hb  = blockIdx.y;
    const int d   = threadIdx.x;
    const int s   = row & (SS - 1);

    if (hb >= NH + NKV) {
        const int h = hb - NH - NKV;
        float f = qkv[(size_t)row * NQKV + 2560 + h * HD + d];
        vh[((size_t)row * NKV + h) * HD + d] = __float2half_rn(f);
        return;
    }

    const bool isQ = (hb < NH);
    const int h = isQ ? hb : hb - NH;
    const int coloff = isQ ? 0 : 2048;
    const float* w = isQ ? qn : kn;
    const float prescale = isQ ? 0.08838834764831845f : 1.0f;

    float val = qkv[(size_t)row * NQKV + coloff + h * HD + d];

    float ss = val * val;
#pragma unroll
    for (int off = 16; off > 0; off >>= 1)
        ss += __shfl_xor_sync(0xffffffffu, ss, off);

    __shared__ float red[4];
    __shared__ float xs[128];
    const int warp = d >> 5, lane = d & 31;
    if (lane == 0) red[warp] = ss;
    __syncthreads();
    float tot = red[0] + red[1] + red[2] + red[3];
    float xn  = val * rsqrtf(tot * (1.0f / 128.0f) + 1e-5f) * w[d];
    xs[d] = xn;
    __syncthreads();

    const int i = d & 63;
    float inv_freq = expf(-(float)i * (13.122363377404328f / 64.0f));
    float ang = (float)s * inv_freq;
    float sn, cs;
    sincosf(ang, &sn, &cs);

    float other = xs[d ^ 64];
    float res = (d < 64) ? (xn * cs - other * sn) : (xn * cs + other * sn);
    res *= prescale;

    __half hv = __float2half_rn(res);
    if (isQ) {
        const size_t obase = ((size_t)row * NH + h) * HD;
        qhi[obase + d] = hv;
        qlo[obase + d] = __float2half_rn(res - __half2float(hv));
    } else {
        kh[((size_t)row * NKV + h) * HD + d] = hv;
    }
}

// ---------------------------------------------------------------------------
// fp16 1-pass GEMM: C[M][N] = Ahi[M][K] * Bhi[N][K]^T (fp32 out)
// BM=BN=128, BK=32, 512 threads (16 warps 4x4), warp tile 32x32.
// 4-stage cp.async pipeline (16KB/stage), ONE sync per chunk.
// ---------------------------------------------------------------------------
#define GS_AH 0
#define GS_BH 8192
#define GS_STAGE 16384
#define GS_SMEM (4 * GS_STAGE)

__global__ void __launch_bounds__(512) gemm_fp16(
    const __half* __restrict__ Ahi, const __half* __restrict__ Bhi,
    float* __restrict__ C, int M, int N, int K)
{
    extern __shared__ char smem[];
    const uint32_t sb = smem_to_u32(smem);

    const int t = threadIdx.x;
    const int lane = t & 31, wid = t >> 5;
    const int bm = blockIdx.y * 128, bn = blockIdx.x * 128;
    const int wm = (wid & 3) * 32;
    const int wn = (wid >> 2) * 32;

    const int lrow = t >> 2, lc = t & 3;
    const size_t ga = (size_t)(bm + lrow) * K + lc * 8;
    const size_t gb = (size_t)(bn + lrow) * K + lc * 8;
    const uint32_t st = swz(lrow, lc);
    const int nch = K >> 5;

    auto issue = [&](int ch) {
        uint32_t base = sb + (uint32_t)(ch & 3) * GS_STAGE + st;
        size_t ka = ga + (size_t)ch * 32;
        size_t kb = gb + (size_t)ch * 32;
        cp_async16(base + GS_AH, Ahi + ka);
        cp_async16(base + GS_BH, Bhi + kb);
    };

    issue(0); CP_COMMIT();
    issue(1); CP_COMMIT();
    issue(2); CP_COMMIT();

    float acc[2][4][4];
#pragma unroll
    for (int i = 0; i < 2; i++)
#pragma unroll
        for (int j = 0; j < 4; j++)
#pragma unroll
            for (int q = 0; q < 4; q++) acc[i][j][q] = 0.0f;

    for (int ch = 0; ch < nch; ch++) {
        CP_WAIT(2);
        __syncthreads();
        if (ch + 3 < nch) { issue(ch + 3); CP_COMMIT(); }

        const uint32_t base = sb + (uint32_t)(ch & 3) * GS_STAGE;
#pragma unroll
        for (int ks = 0; ks < 2; ks++) {
            uint32_t ah[2][4];
#pragma unroll
            for (int mt = 0; mt < 2; mt++) {
                int row = wm + mt * 16 + (lane & 15);
                int c = ks * 2 + (lane >> 4);
                ldsm_x4(ah[mt], base + GS_AH + swz(row, c));
            }
#pragma unroll
            for (int np = 0; np < 2; np++) {
                uint32_t bh[4];
                int row = wn + np * 16 + (lane & 7) + ((lane >> 4) & 1) * 8;
                int c = ks * 2 + ((lane >> 3) & 1);
                ldsm_x4(bh, base + GS_BH + swz(row, c));
#pragma unroll
                for (int half = 0; half < 2; half++) {
                    int nt = np * 2 + half, pb = half * 2;
#pragma unroll
                    for (int mt = 0; mt < 2; mt++)
                        mma16816h(acc[mt][nt], ah[mt], bh[pb], bh[pb + 1]);
                }
            }
        }
    }

#pragma unroll
    for (int mt = 0; mt < 2; mt++)
#pragma unroll
        for (int nt = 0; nt < 4; nt++) {
            int r0 = bm + wm + mt * 16 + (lane >> 2);
            int c0 = bn + wn + nt * 8 + (lane & 3) * 2;
            float2 v0 = make_float2(acc[mt][nt][0], acc[mt][nt][1]);
            float2 v1 = make_float2(acc[mt][nt][2], acc[mt][nt][3]);
            *(float2*)&C[(size_t)r0 * N + c0] = v0;
            *(float2*)&C[(size_t)(r0 + 8) * N + c0] = v1;
        }
}

// ---------------------------------------------------------------------------
// Tensor-core causal flash attention, GQA.
// QK^T: fp16 2-pass (Qhi+Qlo x Khi). PV: fp16 1-pass (Phi x Vhi).
// BM=128, BN=64, D=128. 256 threads = 8 warps; warp tile m16 x n64.
// Epilogue writes fp16 hi only (feeds 1-pass O projection).
// ---------------------------------------------------------------------------
#define SQ_HI 0
#define SQ_LO 32768
#define KV_BASE 65536
#define ST_KH 0
#define ST_VH 16384
#define KV_STAGE 32768
#define FL_SMEM (KV_BASE + 2 * KV_STAGE)

__global__ void __launch_bounds__(256) flash_attn_tc(
    const __half* __restrict__ qhi, const __half* __restrict__ qlo,
    const __half* __restrict__ kh, const __half* __restrict__ vh,
    __half* __restrict__ ohi)
{
    extern __shared__ char smem[];
    const uint32_t sb = smem_to_u32(smem);
    const int t = threadIdx.x, lane = t & 31, wid = t >> 5;
    const int qb = gridDim.x - 1 - blockIdx.x;   // heavy blocks first
    const int h = blockIdx.y, b = blockIdx.z;
    const int kvh = h >> 2;
    const int warp_m = wid * 16;
    const int QSTR = NH * HD;
    const int KSTR = NKV * HD;

    const int cr = t >> 4, cc = t & 15;
    const __half* kh0 = kh + ((size_t)(b * SS)) * KSTR + kvh * HD;
    const __half* vh0 = vh + ((size_t)(b * SS)) * KSTR + kvh * HD;

    auto issue_kv = [&](int kb) {
        uint32_t stage = sb + KV_BASE + (uint32_t)(kb & 1) * KV_STAGE;
#pragma unroll
        for (int i = 0; i < 4; i++) {
            int r = cr + i * 16;
            size_t g = (size_t)(kb * 64 + r) * KSTR + cc * 8;
            uint32_t s = swz256(r, cc);
            cp_async16(stage + ST_KH + s, kh0 + g);
            cp_async16(stage + ST_VH + s, vh0 + g);
        }
    };

    issue_kv(0); CP_COMMIT();

    {
        const __half* qh = qhi + ((size_t)(b * SS + qb * 128)) * QSTR + h * HD;
        const __half* ql = qlo + ((size_t)(b * SS + qb * 128)) * QSTR + h * HD;
#pragma unroll
        for (int i = 0; i < 8; i++) {
            int u = t + i * 256;
            int r = u >> 4, c = u & 15;
            size_t g = (size_t)r * QSTR + c * 8;
            uint32_t s = swz256(r, c);
            *(uint4*)(smem + SQ_HI + s) = *(const uint4*)(qh + g);
            *(uint4*)(smem + SQ_LO + s) = *(const uint4*)(ql + g);
        }
    }

    float m0 = -INFINITY, m1 = -INFINITY, l0 = 0.0f, l1 = 0.0f;
    float oacc[16][4];
#pragma unroll
    for (int i = 0; i < 16; i++)
#pragma unroll
        for (int j = 0; j < 4; j++) oacc[i][j] = 0.0f;

    const int row_lo = qb * 128 + warp_m + (lane >> 2);
    const int nkb = 2 * qb + 2;

    for (int kb = 0; kb < nkb; kb++) {
        CP_WAIT(0);
        __syncthreads();
        if (kb + 1 < nkb) { issue_kv(kb + 1); CP_COMMIT(); }

        if (kb * 64 > qb * 128 + warp_m + 15) continue;
        const bool need_mask = (kb * 64 + 63 > qb * 128 + warp_m);
        const uint32_t stage = sb + KV_BASE + (uint32_t)(kb & 1) * KV_STAGE;

        float sacc[8][4];
#pragma unroll
        for (int i = 0; i < 8; i++)
#pragma unroll
            for (int j = 0; j < 4; j++) sacc[i][j] = 0.0f;

#pragma unroll
        for (int ks = 0; ks < 8; ks++) {
            uint32_t ah[4], al[4];
            {
                int ar = warp_m + (lane & 15);
                int ac = ks * 2 + (lane >> 4);
                uint32_t off = swz256(ar, ac);
                ldsm_x4(ah, sb + SQ_HI + off);
                ldsm_x4(al, sb + SQ_LO + off);
            }
#pragma unroll
            for (int np = 0; np < 4; np++) {
                uint32_t bh[4];
                int br = np * 16 + (lane & 7) + ((lane >> 4) & 1) * 8;
                int bc = ks * 2 + ((lane >> 3) & 1);
                ldsm_x4(bh, stage + ST_KH + swz256(br, bc));
#pragma unroll
                for (int half = 0; half < 2; half++) {
                    int nt = np * 2 + half, pb = half * 2;
                    mma16816h(sacc[nt], ah, bh[pb], bh[pb + 1]);
                    mma16816h(sacc[nt], al, bh[pb], bh[pb + 1]);
                }
            }
        }

        if (need_mask) {
#pragma unroll
            for (int nt = 0; nt < 8; nt++) {
                int col = kb * 64 + nt * 8 + (lane & 3) * 2;
#pragma unroll
                for (int j = 0; j < 4; j++) {
                    int cc2 = col + (j & 1);
                    int rr = row_lo + ((j >> 1) << 3);
                    if (cc2 > rr) sacc[nt][j] = -INFINITY;
                }
            }
        }

        float mt0 = -INFINITY, mt1 = -INFINITY;
#pragma unroll
        for (int nt = 0; nt < 8; nt++) {
            mt0 = fmaxf(mt0, fmaxf(sacc[nt][0], sacc[nt][1]));
            mt1 = fmaxf(mt1, fmaxf(sacc[nt][2], sacc[nt][3]));
        }
        mt0 = fmaxf(mt0, __shfl_xor_sync(0xffffffffu, mt0, 1));
        mt0 = fmaxf(mt0, __shfl_xor_sync(0xffffffffu, mt0, 2));
        mt1 = fmaxf(mt1, __shfl_xor_sync(0xffffffffu, mt1, 1));
        mt1 = fmaxf(mt1, __shfl_xor_sync(0xffffffffu, mt1, 2));

        float mn0 = fmaxf(m0, mt0), mn1 = fmaxf(m1, mt1);
        float sc0 = __expf(m0 - mn0), sc1 = __expf(m1 - mn1);
        m0 = mn0; m1 = mn1;

        float ps0 = 0.0f, ps1 = 0.0f;
#pragma unroll
        for (int nt = 0; nt < 8; nt++) {
            sacc[nt][0] = __expf(sacc[nt][0] - mn0);
            sacc[nt][1] = __expf(sacc[nt][1] - mn0);
            sacc[nt][2] = __expf(sacc[nt][2] - mn1);
            sacc[nt][3] = __expf(sacc[nt][3] - mn1);
            ps0 += sacc[nt][0] + sacc[nt][1];
            ps1 += sacc[nt][2] + sacc[nt][3];
        }
        ps0 += __shfl_xor_sync(0xffffffffu, ps0, 1);
        ps0 += __shfl_xor_sync(0xffffffffu, ps0, 2);
        ps1 += __shfl_xor_sync(0xffffffffu, ps1, 1);
        ps1 += __shfl_xor_sync(0xffffffffu, ps1, 2);
        l0 = l0 * sc0 + ps0;
        l1 = l1 * sc1 + ps1;

#pragma unroll
        for (int nt = 0; nt < 16; nt++) {
            oacc[nt][0] *= sc0; oacc[nt][1] *= sc0;
            oacc[nt][2] *= sc1; oacc[nt][3] *= sc1;
        }

        // ---- PV: fp16 1-pass (P hi x V hi) ----
#pragma unroll
        for (int ks = 0; ks < 4; ks++) {
            uint32_t phi[4];
            phi[0] = pack2h(sacc[2 * ks][0], sacc[2 * ks][1]);
            phi[1] = pack2h(sacc[2 * ks][2], sacc[2 * ks][3]);
            phi[2] = pack2h(sacc[2 * ks + 1][0], sacc[2 * ks + 1][1]);
            phi[3] = pack2h(sacc[2 * ks + 1][2], sacc[2 * ks + 1][3]);
#pragma unroll
            for (int dp = 0; dp < 8; dp++) {
                uint32_t vh4[4];
                int vr = ks * 16 + (lane & 7) + ((lane >> 3) & 1) * 8;
                int vc = dp * 2 + (lane >> 4);
                ldsm_x4_t(vh4, stage + ST_VH + swz256(vr, vc));
                mma16816h(oacc[dp * 2], phi, vh4[0], vh4[1]);
                mma16816h(oacc[dp * 2 + 1], phi, vh4[2], vh4[3]);
            }
        }
    }

    // ---- epilogue: write fp16 hi only ----
    float il0 = 1.0f / l0, il1 = 1.0f / l1;
    __half* oh = ohi + ((size_t)(b * SS)) * QSTR + h * HD;
    int r0 = qb * 128 + warp_m + (lane >> 2);
#pragma unroll
    for (int nt = 0; nt < 16; nt++) {
        int dim = nt * 8 + (lane & 3) * 2;
        uint32_t h0 = pack2h(oacc[nt][0] * il0, oacc[nt][1] * il0);
        uint32_t h1 = pack2h(oacc[nt][2] * il1, oacc[nt][3] * il1);
        *(uint32_t*)&oh[(size_t)r0 * QSTR + dim] = h0;
        *(uint32_t*)&oh[(size_t)(r0 + 8) * QSTR + dim] = h1;
    }
}

// ---------------------------------------------------------------------------
extern "C" void kernel_launch(void* const* d_in, const int* in_sizes, int n_in,
                              void* d_out, int out_size)
{
    const float* hs  = (const float*)d_in[0];
    const float* q_w = (const float*)d_in[1];
    const float* k_w = (const float*)d_in[2];
    const float* v_w = (const float*)d_in[3];
    const float* o_w = (const float*)d_in[4];
    const float* qn  = (const float*)d_in[5];
    const float* kn  = (const float*)d_in[6];
    float* out = (float*)d_out;

    float* pqkv;
    __half *hsh, *qkvw, *owh, *pah, *pqh, *pql, *pkh, *pvh;
    cudaGetSymbolAddress((void**)&pqkv, g_qkv);
    cudaGetSymbolAddress((void**)&hsh, g_hs_hi);
    cudaGetSymbolAddress((void**)&qkvw, g_qkvw_hi);
    cudaGetSymbolAddress((void**)&owh, g_ow_hi);
    cudaGetSymbolAddress((void**)&pah, g_ahi);
    cudaGetSymbolAddress((void**)&pqh, g_qhi);
    cudaGetSymbolAddress((void**)&pql, g_qlo);
    cudaGetSymbolAddress((void**)&pkh, g_kh);
    cudaGetSymbolAddress((void**)&pvh, g_vh);

    const int M = BB * SS;     // 4096
    const int K = HH;          // 2048

    // fused operand conversion, one launch
    conv_all<<<18432, 256>>>(hs, q_w, k_w, v_w, o_w, hsh, qkvw, owh);

    cudaFuncSetAttribute(gemm_fp16, cudaFuncAttributeMaxDynamicSharedMemorySize,
                         GS_SMEM);

    // fused QKV projection: one GEMM, N = 3072 (1-pass fp16)
    gemm_fp16<<<dim3(NQKV / 128, M / 128), 512, GS_SMEM>>>(hsh, qkvw,
                                                           pqkv, M, NQKV, K);

    // fused rmsnorm+rope (Q fp16 hi/lo, K fp16 hi) + V convert: one launch
    norm_split<<<dim3(M, NH + NKV + NKV), 128>>>(pqkv, qn, kn,
                                                 pqh, pql, pkh, pvh);

    // tensor-core causal flash attention (QK 2-pass, PV 1-pass fp16)
    cudaFuncSetAttribute(flash_attn_tc, cudaFuncAttributeMaxDynamicSharedMemorySize,
                         FL_SMEM);
    flash_attn_tc<<<dim3(SS / 128, NH, BB), 256, FL_SMEM>>>(pqh, pql, pkh, pvh,
                                                            pah);

    // output projection (1-pass fp16)
    gemm_fp16<<<dim3(HH / 128, M / 128), 512, GS_SMEM>>>(pah, owh,
                                                         out, M, HH, K);
}

// round 14
// speedup vs baseline: 1.6946x; 1.0405x over previous
#include <cuda_runtime.h>
#include <cuda_bf16.h>
#include <cuda_fp16.h>
#include <stdint.h>
#include <math.h>

#define BB 2
#define SS 2048
#define HH 2048
#define NH 16
#define NKV 4
#define HD 128
#define NQKV 3072   // fused QKV output width: 2048 + 512 + 512

// ---------------- scratch (device globals: allocation-free) ----------------
__device__ float g_qkv[(size_t)BB * SS * NQKV];      // fused QKV projection out
// fp16 GEMM operands (1-pass: hi only both sides)
__device__ __half g_hs_hi[(size_t)BB * SS * HH];
__device__ __half g_qkvw_hi[(size_t)NQKV * HH];      // fused QKV weights
__device__ __half g_ow_hi[(size_t)HH * NH * HD];
// post-norm attention operands: Q/K/V fp16 (1-pass attention)
__device__ __half g_qhi[(size_t)BB * SS * NH * HD];
__device__ __half g_kh[(size_t)BB * SS * NKV * HD];
__device__ __half g_vh[(size_t)BB * SS * NKV * HD];
// attention output (fp16, feeds 1-pass O projection)
__device__ __half g_ahi[(size_t)BB * SS * NH * HD];

// ===================== warp-MMA helpers =====================
__device__ __forceinline__ uint32_t smem_to_u32(const void* p) {
    uint32_t a;
    asm("{ .reg .u64 t; cvta.to.shared.u64 t, %1; cvt.u32.u64 %0, t; }"
        : "=r"(a) : "l"(p));
    return a;
}
__device__ __forceinline__ void ldsm_x4(uint32_t r[4], uint32_t addr) {
    asm volatile("ldmatrix.sync.aligned.m8n8.x4.shared.b16 {%0,%1,%2,%3}, [%4];"
                 : "=r"(r[0]), "=r"(r[1]), "=r"(r[2]), "=r"(r[3]) : "r"(addr));
}
__device__ __forceinline__ void ldsm_x4_t(uint32_t r[4], uint32_t addr) {
    asm volatile("ldmatrix.sync.aligned.m8n8.x4.trans.shared.b16 {%0,%1,%2,%3}, [%4];"
                 : "=r"(r[0]), "=r"(r[1]), "=r"(r[2]), "=r"(r[3]) : "r"(addr));
}
// fp16 MMA
__device__ __forceinline__ void mma16816h(float c[4], const uint32_t a[4],
                                          const uint32_t b0, const uint32_t b1) {
    asm volatile(
        "mma.sync.aligned.m16n8k16.row.col.f32.f16.f16.f32 "
        "{%0,%1,%2,%3}, {%4,%5,%6,%7}, {%8,%9}, {%0,%1,%2,%3};"
        : "+f"(c[0]), "+f"(c[1]), "+f"(c[2]), "+f"(c[3])
        : "r"(a[0]), "r"(a[1]), "r"(a[2]), "r"(a[3]), "r"(b0), "r"(b1));
}
__device__ __forceinline__ void cp_async16(uint32_t dst, const void* src) {
    asm volatile("cp.async.cg.shared.global [%0], [%1], 16;"
                 :: "r"(dst), "l"(src) : "memory");
}
#define CP_COMMIT() asm volatile("cp.async.commit_group;" ::: "memory")
#define CP_WAIT(n)  asm volatile("cp.async.wait_group %0;" :: "n"(n) : "memory")

__device__ __forceinline__ uint32_t pack2h(float x, float y) {
    return (uint32_t)__half_as_ushort(__float2half_rn(x))
         | ((uint32_t)__half_as_ushort(__float2half_rn(y)) << 16);
}

// swizzled byte offset in a [rows x 32 elems] 16-bit tile (64B rows, 4x16B units)
__device__ __forceinline__ uint32_t swz(int row, int c) {
    return (uint32_t)(row * 64 + ((c ^ ((row >> 1) & 3)) << 4));
}
// swizzled byte offset in a [rows x 128 elems] 16-bit tile (256B rows, 16x16B units)
__device__ __forceinline__ uint32_t swz256(int row, int c) {
    return (uint32_t)(row * 256 + ((c ^ (row & 7)) << 4));
}

// ---------------------------------------------------------------------------
// fused converter: one launch, all 5 fp32->fp16 converts.
// ---------------------------------------------------------------------------
__global__ void conv_all(const float* __restrict__ hs,
                         const float* __restrict__ qw, const float* __restrict__ kw,
                         const float* __restrict__ vw, const float* __restrict__ ow,
                         __half* __restrict__ hsh,
                         __half* __restrict__ qkvw, __half* __restrict__ owh)
{
    const int blk = blockIdx.x;
    const float* src;
    __half* dst;
    int base;
    if (blk < 8192)       { src = hs; dst = hsh;                       base = blk; }
    else if (blk < 12288) { src = qw; dst = qkvw;                      base = blk - 8192; }
    else if (blk < 13312) { src = kw; dst = qkvw + (size_t)2048 * HH;  base = blk - 12288; }
    else if (blk < 14336) { src = vw; dst = qkvw + (size_t)2560 * HH;  base = blk - 13312; }
    else                  { src = ow; dst = owh;                       base = blk - 14336; }
    size_t i = ((size_t)base * 256 + threadIdx.x) * 4;
    float4 f = *(const float4*)(src + i);
    uint2 h;
    h.x = pack2h(f.x, f.y);
    h.y = pack2h(f.z, f.w);
    *(uint2*)(dst + i) = h;
}

// ---------------------------------------------------------------------------
// Fused pre-attention kernel: grid (M, NH+NKV+NKV).
//   blockIdx.y <  NH          : Q rmsnorm+rope -> fp16 (prescaled)
//   blockIdx.y in [NH, NH+NKV): K rmsnorm+rope -> fp16
//   blockIdx.y >= NH+NKV      : V -> fp16
// ---------------------------------------------------------------------------
__global__ void norm_split(const float* __restrict__ qkv,
                           const float* __restrict__ qn, const float* __restrict__ kn,
                           __half* __restrict__ qhi,
                           __half* __restrict__ kh, __half* __restrict__ vh)
{
    const int row = blockIdx.x;
    const int hb  = blockIdx.y;
    const int d   = threadIdx.x;
    const int s   = row & (SS - 1);

    if (hb >= NH + NKV) {
        const int h = hb - NH - NKV;
        float f = qkv[(size_t)row * NQKV + 2560 + h * HD + d];
        vh[((size_t)row * NKV + h) * HD + d] = __float2half_rn(f);
        return;
    }

    const bool isQ = (hb < NH);
    const int h = isQ ? hb : hb - NH;
    const int coloff = isQ ? 0 : 2048;
    const float* w = isQ ? qn : kn;
    const float prescale = isQ ? 0.08838834764831845f : 1.0f;

    float val = qkv[(size_t)row * NQKV + coloff + h * HD + d];

    float ss = val * val;
#pragma unroll
    for (int off = 16; off > 0; off >>= 1)
        ss += __shfl_xor_sync(0xffffffffu, ss, off);

    __shared__ float red[4];
    __shared__ float xs[128];
    const int warp = d >> 5, lane = d & 31;
    if (lane == 0) red[warp] = ss;
    __syncthreads();
    float tot = red[0] + red[1] + red[2] + red[3];
    float xn  = val * rsqrtf(tot * (1.0f / 128.0f) + 1e-5f) * w[d];
    xs[d] = xn;
    __syncthreads();

    const int i = d & 63;
    float inv_freq = expf(-(float)i * (13.122363377404328f / 64.0f));
    float ang = (float)s * inv_freq;
    float sn, cs;
    sincosf(ang, &sn, &cs);

    float other = xs[d ^ 64];
    float res = (d < 64) ? (xn * cs - other * sn) : (xn * cs + other * sn);
    res *= prescale;

    __half hv = __float2half_rn(res);
    if (isQ) {
        qhi[((size_t)row * NH + h) * HD + d] = hv;
    } else {
        kh[((size_t)row * NKV + h) * HD + d] = hv;
    }
}

// ---------------------------------------------------------------------------
// fp16 1-pass GEMM: C[M][N] = Ahi[M][K] * Bhi[N][K]^T (fp32 out)
// BM=BN=128, BK=32, 512 threads (16 warps 4x4), warp tile 32x32.
// 4-stage cp.async pipeline (16KB/stage), ONE sync per chunk.
// ---------------------------------------------------------------------------
#define GS_AH 0
#define GS_BH 8192
#define GS_STAGE 16384
#define GS_SMEM (4 * GS_STAGE)

__global__ void __launch_bounds__(512) gemm_fp16(
    const __half* __restrict__ Ahi, const __half* __restrict__ Bhi,
    float* __restrict__ C, int M, int N, int K)
{
    extern __shared__ char smem[];
    const uint32_t sb = smem_to_u32(smem);

    const int t = threadIdx.x;
    const int lane = t & 31, wid = t >> 5;
    const int bm = blockIdx.y * 128, bn = blockIdx.x * 128;
    const int wm = (wid & 3) * 32;
    const int wn = (wid >> 2) * 32;

    const int lrow = t >> 2, lc = t & 3;
    const size_t ga = (size_t)(bm + lrow) * K + lc * 8;
    const size_t gb = (size_t)(bn + lrow) * K + lc * 8;
    const uint32_t st = swz(lrow, lc);
    const int nch = K >> 5;

    auto issue = [&](int ch) {
        uint32_t base = sb + (uint32_t)(ch & 3) * GS_STAGE + st;
        size_t ka = ga + (size_t)ch * 32;
        size_t kb = gb + (size_t)ch * 32;
        cp_async16(base + GS_AH, Ahi + ka);
        cp_async16(base + GS_BH, Bhi + kb);
    };

    issue(0); CP_COMMIT();
    issue(1); CP_COMMIT();
    issue(2); CP_COMMIT();

    float acc[2][4][4];
#pragma unroll
    for (int i = 0; i < 2; i++)
#pragma unroll
        for (int j = 0; j < 4; j++)
#pragma unroll
            for (int q = 0; q < 4; q++) acc[i][j][q] = 0.0f;

    for (int ch = 0; ch < nch; ch++) {
        CP_WAIT(2);
        __syncthreads();
        if (ch + 3 < nch) { issue(ch + 3); CP_COMMIT(); }

        const uint32_t base = sb + (uint32_t)(ch & 3) * GS_STAGE;
#pragma unroll
        for (int ks = 0; ks < 2; ks++) {
            uint32_t ah[2][4];
#pragma unroll
            for (int mt = 0; mt < 2; mt++) {
                int row = wm + mt * 16 + (lane & 15);
                int c = ks * 2 + (lane >> 4);
                ldsm_x4(ah[mt], base + GS_AH + swz(row, c));
            }
#pragma unroll
            for (int np = 0; np < 2; np++) {
                uint32_t bh[4];
                int row = wn + np * 16 + (lane & 7) + ((lane >> 4) & 1) * 8;
                int c = ks * 2 + ((lane >> 3) & 1);
                ldsm_x4(bh, base + GS_BH + swz(row, c));
#pragma unroll
                for (int half = 0; half < 2; half++) {
                    int nt = np * 2 + half, pb = half * 2;
#pragma unroll
                    for (int mt = 0; mt < 2; mt++)
                        mma16816h(acc[mt][nt], ah[mt], bh[pb], bh[pb + 1]);
                }
            }
        }
    }

#pragma unroll
    for (int mt = 0; mt < 2; mt++)
#pragma unroll
        for (int nt = 0; nt < 4; nt++) {
            int r0 = bm + wm + mt * 16 + (lane >> 2);
            int c0 = bn + wn + nt * 8 + (lane & 3) * 2;
            float2 v0 = make_float2(acc[mt][nt][0], acc[mt][nt][1]);
            float2 v1 = make_float2(acc[mt][nt][2], acc[mt][nt][3]);
            *(float2*)&C[(size_t)r0 * N + c0] = v0;
            *(float2*)&C[(size_t)(r0 + 8) * N + c0] = v1;
        }
}

// ---------------------------------------------------------------------------
// Tensor-core causal flash attention, GQA — fully fp16 1-pass.
// Q fragments hoisted to registers (staged once through stage-0 smem).
// BM=128, BN=64, D=128. 256 threads = 8 warps; warp tile m16 x n64.
// smem = 2 x 32KB KV stages only.
// ---------------------------------------------------------------------------
#define ST_KH 0
#define ST_VH 16384
#define KV_STAGE 32768
#define FL_SMEM (2 * KV_STAGE)

__global__ void __launch_bounds__(256) flash_attn_tc(
    const __half* __restrict__ qhi,
    const __half* __restrict__ kh, const __half* __restrict__ vh,
    __half* __restrict__ ohi)
{
    extern __shared__ char smem[];
    const uint32_t sb = smem_to_u32(smem);
    const int t = threadIdx.x, lane = t & 31, wid = t >> 5;
    const int qb = gridDim.x - 1 - blockIdx.x;   // heavy blocks first
    const int h = blockIdx.y, b = blockIdx.z;
    const int kvh = h >> 2;
    const int warp_m = wid * 16;
    const int QSTR = NH * HD;
    const int KSTR = NKV * HD;

    // ---- stage Q (128x128 fp16 = 32KB) through stage-0 smem, hoist frags ----
    {
        const __half* qh = qhi + ((size_t)(b * SS + qb * 128)) * QSTR + h * HD;
#pragma unroll
        for (int i = 0; i < 8; i++) {
            int u = t + i * 256;
            int r = u >> 4, c = u & 15;
            *(uint4*)(smem + swz256(r, c)) =
                *(const uint4*)(qh + (size_t)r * QSTR + c * 8);
        }
    }
    __syncthreads();
    uint32_t qf[8][4];
#pragma unroll
    for (int ks = 0; ks < 8; ks++) {
        int ar = warp_m + (lane & 15);
        int ac = ks * 2 + (lane >> 4);
        ldsm_x4(qf[ks], sb + swz256(ar, ac));
    }
    __syncthreads();   // all frags extracted; smem free for KV stages

    const int cr = t >> 4, cc = t & 15;
    const __half* kh0 = kh + ((size_t)(b * SS)) * KSTR + kvh * HD;
    const __half* vh0 = vh + ((size_t)(b * SS)) * KSTR + kvh * HD;

    auto issue_kv = [&](int kb) {
        uint32_t stage = sb + (uint32_t)(kb & 1) * KV_STAGE;
#pragma unroll
        for (int i = 0; i < 4; i++) {
            int r = cr + i * 16;
            size_t g = (size_t)(kb * 64 + r) * KSTR + cc * 8;
            uint32_t s = swz256(r, cc);
            cp_async16(stage + ST_KH + s, kh0 + g);
            cp_async16(stage + ST_VH + s, vh0 + g);
        }
    };

    issue_kv(0); CP_COMMIT();

    float m0 = -INFINITY, m1 = -INFINITY, l0 = 0.0f, l1 = 0.0f;
    float oacc[16][4];
#pragma unroll
    for (int i = 0; i < 16; i++)
#pragma unroll
        for (int j = 0; j < 4; j++) oacc[i][j] = 0.0f;

    const int row_lo = qb * 128 + warp_m + (lane >> 2);
    const int nkb = 2 * qb + 2;

    for (int kb = 0; kb < nkb; kb++) {
        CP_WAIT(0);
        __syncthreads();
        if (kb + 1 < nkb) { issue_kv(kb + 1); CP_COMMIT(); }

        if (kb * 64 > qb * 128 + warp_m + 15) continue;
        const bool need_mask = (kb * 64 + 63 > qb * 128 + warp_m);
        const uint32_t stage = sb + (uint32_t)(kb & 1) * KV_STAGE;

        float sacc[8][4];
#pragma unroll
        for (int i = 0; i < 8; i++)
#pragma unroll
            for (int j = 0; j < 4; j++) sacc[i][j] = 0.0f;

        // ---- S = Q K^T (fp16 1-pass, Q from registers) ----
#pragma unroll
        for (int ks = 0; ks < 8; ks++) {
#pragma unroll
            for (int np = 0; np < 4; np++) {
                uint32_t bh[4];
                int br = np * 16 + (lane & 7) + ((lane >> 4) & 1) * 8;
                int bc = ks * 2 + ((lane >> 3) & 1);
                ldsm_x4(bh, stage + ST_KH + swz256(br, bc));
                mma16816h(sacc[np * 2 + 0], qf[ks], bh[0], bh[1]);
                mma16816h(sacc[np * 2 + 1], qf[ks], bh[2], bh[3]);
            }
        }

        if (need_mask) {
#pragma unroll
            for (int nt = 0; nt < 8; nt++) {
                int col = kb * 64 + nt * 8 + (lane & 3) * 2;
#pragma unroll
                for (int j = 0; j < 4; j++) {
                    int cc2 = col + (j & 1);
                    int rr = row_lo + ((j >> 1) << 3);
                    if (cc2 > rr) sacc[nt][j] = -INFINITY;
                }
            }
        }

        float mt0 = -INFINITY, mt1 = -INFINITY;
#pragma unroll
        for (int nt = 0; nt < 8; nt++) {
            mt0 = fmaxf(mt0, fmaxf(sacc[nt][0], sacc[nt][1]));
            mt1 = fmaxf(mt1, fmaxf(sacc[nt][2], sacc[nt][3]));
        }
        mt0 = fmaxf(mt0, __shfl_xor_sync(0xffffffffu, mt0, 1));
        mt0 = fmaxf(mt0, __shfl_xor_sync(0xffffffffu, mt0, 2));
        mt1 = fmaxf(mt1, __shfl_xor_sync(0xffffffffu, mt1, 1));
        mt1 = fmaxf(mt1, __shfl_xor_sync(0xffffffffu, mt1, 2));

        float mn0 = fmaxf(m0, mt0), mn1 = fmaxf(m1, mt1);
        float sc0 = __expf(m0 - mn0), sc1 = __expf(m1 - mn1);
        m0 = mn0; m1 = mn1;

        float ps0 = 0.0f, ps1 = 0.0f;
#pragma unroll
        for (int nt = 0; nt < 8; nt++) {
            sacc[nt][0] = __expf(sacc[nt][0] - mn0);
            sacc[nt][1] = __expf(sacc[nt][1] - mn0);
            sacc[nt][2] = __expf(sacc[nt][2] - mn1);
            sacc[nt][3] = __expf(sacc[nt][3] - mn1);
            ps0 += sacc[nt][0] + sacc[nt][1];
            ps1 += sacc[nt][2] + sacc[nt][3];
        }
        ps0 += __shfl_xor_sync(0xffffffffu, ps0, 1);
        ps0 += __shfl_xor_sync(0xffffffffu, ps0, 2);
        ps1 += __shfl_xor_sync(0xffffffffu, ps1, 1);
        ps1 += __shfl_xor_sync(0xffffffffu, ps1, 2);
        l0 = l0 * sc0 + ps0;
        l1 = l1 * sc1 + ps1;

#pragma unroll
        for (int nt = 0; nt < 16; nt++) {
            oacc[nt][0] *= sc0; oacc[nt][1] *= sc0;
            oacc[nt][2] *= sc1; oacc[nt][3] *= sc1;
        }

        // ---- PV: fp16 1-pass (P hi x V hi) ----
#pragma unroll
        for (int ks = 0; ks < 4; ks++) {
            uint32_t phi[4];
            phi[0] = pack2h(sacc[2 * ks][0], sacc[2 * ks][1]);
            phi[1] = pack2h(sacc[2 * ks][2], sacc[2 * ks][3]);
            phi[2] = pack2h(sacc[2 * ks + 1][0], sacc[2 * ks + 1][1]);
            phi[3] = pack2h(sacc[2 * ks + 1][2], sacc[2 * ks + 1][3]);
#pragma unroll
            for (int dp = 0; dp < 8; dp++) {
                uint32_t vh4[4];
                int vr = ks * 16 + (lane & 7) + ((lane >> 3) & 1) * 8;
                int vc = dp * 2 + (lane >> 4);
                ldsm_x4_t(vh4, stage + ST_VH + swz256(vr, vc));
                mma16816h(oacc[dp * 2], phi, vh4[0], vh4[1]);
                mma16816h(oacc[dp * 2 + 1], phi, vh4[2], vh4[3]);
            }
        }
    }

    // ---- epilogue: write fp16 ----
    float il0 = 1.0f / l0, il1 = 1.0f / l1;
    __half* oh = ohi + ((size_t)(b * SS)) * QSTR + h * HD;
    int r0 = qb * 128 + warp_m + (lane >> 2);
#pragma unroll
    for (int nt = 0; nt < 16; nt++) {
        int dim = nt * 8 + (lane & 3) * 2;
        uint32_t h0 = pack2h(oacc[nt][0] * il0, oacc[nt][1] * il0);
        uint32_t h1 = pack2h(oacc[nt][2] * il1, oacc[nt][3] * il1);
        *(uint32_t*)&oh[(size_t)r0 * QSTR + dim] = h0;
        *(uint32_t*)&oh[(size_t)(r0 + 8) * QSTR + dim] = h1;
    }
}

// ---------------------------------------------------------------------------
extern "C" void kernel_launch(void* const* d_in, const int* in_sizes, int n_in,
                              void* d_out, int out_size)
{
    const float* hs  = (const float*)d_in[0];
    const float* q_w = (const float*)d_in[1];
    const float* k_w = (const float*)d_in[2];
    const float* v_w = (const float*)d_in[3];
    const float* o_w = (const float*)d_in[4];
    const float* qn  = (const float*)d_in[5];
    const float* kn  = (const float*)d_in[6];
    float* out = (float*)d_out;

    float* pqkv;
    __half *hsh, *qkvw, *owh, *pah, *pqh, *pkh, *pvh;
    cudaGetSymbolAddress((void**)&pqkv, g_qkv);
    cudaGetSymbolAddress((void**)&hsh, g_hs_hi);
    cudaGetSymbolAddress((void**)&qkvw, g_qkvw_hi);
    cudaGetSymbolAddress((void**)&owh, g_ow_hi);
    cudaGetSymbolAddress((void**)&pah, g_ahi);
    cudaGetSymbolAddress((void**)&pqh, g_qhi);
    cudaGetSymbolAddress((void**)&pkh, g_kh);
    cudaGetSymbolAddress((void**)&pvh, g_vh);

    const int M = BB * SS;     // 4096
    const int K = HH;          // 2048

    // fused operand conversion, one launch
    conv_all<<<18432, 256>>>(hs, q_w, k_w, v_w, o_w, hsh, qkvw, owh);

    cudaFuncSetAttribute(gemm_fp16, cudaFuncAttributeMaxDynamicSharedMemorySize,
                         GS_SMEM);

    // fused QKV projection: one GEMM, N = 3072 (1-pass fp16)
    gemm_fp16<<<dim3(NQKV / 128, M / 128), 512, GS_SMEM>>>(hsh, qkvw,
                                                           pqkv, M, NQKV, K);

    // fused rmsnorm+rope + V convert: one launch
    norm_split<<<dim3(M, NH + NKV + NKV), 128>>>(pqkv, qn, kn, pqh, pkh, pvh);

    // tensor-core causal flash attention (1-pass fp16, Q in registers)
    cudaFuncSetAttribute(flash_attn_tc, cudaFuncAttributeMaxDynamicSharedMemorySize,
                         FL_SMEM);
    flash_attn_tc<<<dim3(SS / 128, NH, BB), 256, FL_SMEM>>>(pqh, pkh, pvh, pah);

    // output projection (1-pass fp16)
    gemm_fp16<<<dim3(HH / 128, M / 128), 512, GS_SMEM>>>(pah, owh,
                                                         out, M, HH, K);
}

// round 15
// speedup vs baseline: 1.7736x; 1.0466x over previous
#include <cuda_runtime.h>
#include <cuda_bf16.h>
#include <cuda_fp16.h>
#include <stdint.h>
#include <math.h>

#define BB 2
#define SS 2048
#define HH 2048
#define NH 16
#define NKV 4
#define HD 128
#define NQKV 3072   // fused QKV output width: 2048 + 512 + 512

// ---------------- scratch (device globals: allocation-free) ----------------
__device__ float g_qkv[(size_t)BB * SS * NQKV];      // fused QKV projection out
// fp16 GEMM operands (1-pass: hi only both sides)
__device__ __half g_hs_hi[(size_t)BB * SS * HH];
__device__ __half g_qkvw_hi[(size_t)NQKV * HH];      // fused QKV weights
__device__ __half g_ow_hi[(size_t)HH * NH * HD];
// post-norm attention operands: Q/K/V fp16 (1-pass attention)
__device__ __half g_qhi[(size_t)BB * SS * NH * HD];
__device__ __half g_kh[(size_t)BB * SS * NKV * HD];
__device__ __half g_vh[(size_t)BB * SS * NKV * HD];
// attention output (fp16, feeds 1-pass O projection)
__device__ __half g_ahi[(size_t)BB * SS * NH * HD];

// ===================== warp-MMA helpers =====================
__device__ __forceinline__ uint32_t smem_to_u32(const void* p) {
    uint32_t a;
    asm("{ .reg .u64 t; cvta.to.shared.u64 t, %1; cvt.u32.u64 %0, t; }"
        : "=r"(a) : "l"(p));
    return a;
}
__device__ __forceinline__ void ldsm_x4(uint32_t r[4], uint32_t addr) {
    asm volatile("ldmatrix.sync.aligned.m8n8.x4.shared.b16 {%0,%1,%2,%3}, [%4];"
                 : "=r"(r[0]), "=r"(r[1]), "=r"(r[2]), "=r"(r[3]) : "r"(addr));
}
__device__ __forceinline__ void ldsm_x4_t(uint32_t r[4], uint32_t addr) {
    asm volatile("ldmatrix.sync.aligned.m8n8.x4.trans.shared.b16 {%0,%1,%2,%3}, [%4];"
                 : "=r"(r[0]), "=r"(r[1]), "=r"(r[2]), "=r"(r[3]) : "r"(addr));
}
// fp16 MMA
__device__ __forceinline__ void mma16816h(float c[4], const uint32_t a[4],
                                          const uint32_t b0, const uint32_t b1) {
    asm volatile(
        "mma.sync.aligned.m16n8k16.row.col.f32.f16.f16.f32 "
        "{%0,%1,%2,%3}, {%4,%5,%6,%7}, {%8,%9}, {%0,%1,%2,%3};"
        : "+f"(c[0]), "+f"(c[1]), "+f"(c[2]), "+f"(c[3])
        : "r"(a[0]), "r"(a[1]), "r"(a[2]), "r"(a[3]), "r"(b0), "r"(b1));
}
__device__ __forceinline__ void cp_async16(uint32_t dst, const void* src) {
    asm volatile("cp.async.cg.shared.global [%0], [%1], 16;"
                 :: "r"(dst), "l"(src) : "memory");
}
#define CP_COMMIT() asm volatile("cp.async.commit_group;" ::: "memory")
#define CP_WAIT(n)  asm volatile("cp.async.wait_group %0;" :: "n"(n) : "memory")

__device__ __forceinline__ uint32_t pack2h(float x, float y) {
    return (uint32_t)__half_as_ushort(__float2half_rn(x))
         | ((uint32_t)__half_as_ushort(__float2half_rn(y)) << 16);
}

// swizzled byte offset in a [rows x 32 elems] 16-bit tile (64B rows, 4x16B units)
__device__ __forceinline__ uint32_t swz(int row, int c) {
    return (uint32_t)(row * 64 + ((c ^ ((row >> 1) & 3)) << 4));
}
// swizzled byte offset in a [rows x 128 elems] 16-bit tile (256B rows, 16x16B units)
__device__ __forceinline__ uint32_t swz256(int row, int c) {
    return (uint32_t)(row * 256 + ((c ^ (row & 7)) << 4));
}

// ---------------------------------------------------------------------------
// fused converter: one launch, all 5 fp32->fp16 converts.
// ---------------------------------------------------------------------------
__global__ void conv_all(const float* __restrict__ hs,
                         const float* __restrict__ qw, const float* __restrict__ kw,
                         const float* __restrict__ vw, const float* __restrict__ ow,
                         __half* __restrict__ hsh,
                         __half* __restrict__ qkvw, __half* __restrict__ owh)
{
    const int blk = blockIdx.x;
    const float* src;
    __half* dst;
    int base;
    if (blk < 8192)       { src = hs; dst = hsh;                       base = blk; }
    else if (blk < 12288) { src = qw; dst = qkvw;                      base = blk - 8192; }
    else if (blk < 13312) { src = kw; dst = qkvw + (size_t)2048 * HH;  base = blk - 12288; }
    else if (blk < 14336) { src = vw; dst = qkvw + (size_t)2560 * HH;  base = blk - 13312; }
    else                  { src = ow; dst = owh;                       base = blk - 14336; }
    size_t i = ((size_t)base * 256 + threadIdx.x) * 4;
    float4 f = *(const float4*)(src + i);
    uint2 h;
    h.x = pack2h(f.x, f.y);
    h.y = pack2h(f.z, f.w);
    *(uint2*)(dst + i) = h;
}

// ---------------------------------------------------------------------------
// Fused pre-attention kernel: grid (M, NH+NKV+NKV).
// ---------------------------------------------------------------------------
__global__ void norm_split(const float* __restrict__ qkv,
                           const float* __restrict__ qn, const float* __restrict__ kn,
                           __half* __restrict__ qhi,
                           __half* __restrict__ kh, __half* __restrict__ vh)
{
    const int row = blockIdx.x;
    const int hb  = blockIdx.y;
    const int d   = threadIdx.x;
    const int s   = row & (SS - 1);

    if (hb >= NH + NKV) {
        const int h = hb - NH - NKV;
        float f = qkv[(size_t)row * NQKV + 2560 + h * HD + d];
        vh[((size_t)row * NKV + h) * HD + d] = __float2half_rn(f);
        return;
    }

    const bool isQ = (hb < NH);
    const int h = isQ ? hb : hb - NH;
    const int coloff = isQ ? 0 : 2048;
    const float* w = isQ ? qn : kn;
    const float prescale = isQ ? 0.08838834764831845f : 1.0f;

    float val = qkv[(size_t)row * NQKV + coloff + h * HD + d];

    float ss = val * val;
#pragma unroll
    for (int off = 16; off > 0; off >>= 1)
        ss += __shfl_xor_sync(0xffffffffu, ss, off);

    __shared__ float red[4];
    __shared__ float xs[128];
    const int warp = d >> 5, lane = d & 31;
    if (lane == 0) red[warp] = ss;
    __syncthreads();
    float tot = red[0] + red[1] + red[2] + red[3];
    float xn  = val * rsqrtf(tot * (1.0f / 128.0f) + 1e-5f) * w[d];
    xs[d] = xn;
    __syncthreads();

    const int i = d & 63;
    float inv_freq = expf(-(float)i * (13.122363377404328f / 64.0f));
    float ang = (float)s * inv_freq;
    float sn, cs;
    sincosf(ang, &sn, &cs);

    float other = xs[d ^ 64];
    float res = (d < 64) ? (xn * cs - other * sn) : (xn * cs + other * sn);
    res *= prescale;

    __half hv = __float2half_rn(res);
    if (isQ) {
        qhi[((size_t)row * NH + h) * HD + d] = hv;
    } else {
        kh[((size_t)row * NKV + h) * HD + d] = hv;
    }
}

// ---------------------------------------------------------------------------
// fp16 1-pass GEMM: C[M][N] = Ahi[M][K] * Bhi[N][K]^T (fp32 out)
// ---------------------------------------------------------------------------
#define GS_AH 0
#define GS_BH 8192
#define GS_STAGE 16384
#define GS_SMEM (4 * GS_STAGE)

__global__ void __launch_bounds__(512) gemm_fp16(
    const __half* __restrict__ Ahi, const __half* __restrict__ Bhi,
    float* __restrict__ C, int M, int N, int K)
{
    extern __shared__ char smem[];
    const uint32_t sb = smem_to_u32(smem);

    const int t = threadIdx.x;
    const int lane = t & 31, wid = t >> 5;
    const int bm = blockIdx.y * 128, bn = blockIdx.x * 128;
    const int wm = (wid & 3) * 32;
    const int wn = (wid >> 2) * 32;

    const int lrow = t >> 2, lc = t & 3;
    const size_t ga = (size_t)(bm + lrow) * K + lc * 8;
    const size_t gb = (size_t)(bn + lrow) * K + lc * 8;
    const uint32_t st = swz(lrow, lc);
    const int nch = K >> 5;

    auto issue = [&](int ch) {
        uint32_t base = sb + (uint32_t)(ch & 3) * GS_STAGE + st;
        size_t ka = ga + (size_t)ch * 32;
        size_t kb = gb + (size_t)ch * 32;
        cp_async16(base + GS_AH, Ahi + ka);
        cp_async16(base + GS_BH, Bhi + kb);
    };

    issue(0); CP_COMMIT();
    issue(1); CP_COMMIT();
    issue(2); CP_COMMIT();

    float acc[2][4][4];
#pragma unroll
    for (int i = 0; i < 2; i++)
#pragma unroll
        for (int j = 0; j < 4; j++)
#pragma unroll
            for (int q = 0; q < 4; q++) acc[i][j][q] = 0.0f;

    for (int ch = 0; ch < nch; ch++) {
        CP_WAIT(2);
        __syncthreads();
        if (ch + 3 < nch) { issue(ch + 3); CP_COMMIT(); }

        const uint32_t base = sb + (uint32_t)(ch & 3) * GS_STAGE;
#pragma unroll
        for (int ks = 0; ks < 2; ks++) {
            uint32_t ah[2][4];
#pragma unroll
            for (int mt = 0; mt < 2; mt++) {
                int row = wm + mt * 16 + (lane & 15);
                int c = ks * 2 + (lane >> 4);
                ldsm_x4(ah[mt], base + GS_AH + swz(row, c));
            }
#pragma unroll
            for (int np = 0; np < 2; np++) {
                uint32_t bh[4];
                int row = wn + np * 16 + (lane & 7) + ((lane >> 4) & 1) * 8;
                int c = ks * 2 + ((lane >> 3) & 1);
                ldsm_x4(bh, base + GS_BH + swz(row, c));
#pragma unroll
                for (int half = 0; half < 2; half++) {
                    int nt = np * 2 + half, pb = half * 2;
#pragma unroll
                    for (int mt = 0; mt < 2; mt++)
                        mma16816h(acc[mt][nt], ah[mt], bh[pb], bh[pb + 1]);
                }
            }
        }
    }

#pragma unroll
    for (int mt = 0; mt < 2; mt++)
#pragma unroll
        for (int nt = 0; nt < 4; nt++) {
            int r0 = bm + wm + mt * 16 + (lane >> 2);
            int c0 = bn + wn + nt * 8 + (lane & 3) * 2;
            float2 v0 = make_float2(acc[mt][nt][0], acc[mt][nt][1]);
            float2 v1 = make_float2(acc[mt][nt][2], acc[mt][nt][3]);
            *(float2*)&C[(size_t)r0 * N + c0] = v0;
            *(float2*)&C[(size_t)(r0 + 8) * N + c0] = v1;
        }
}

// ---------------------------------------------------------------------------
// Tensor-core causal flash attention, GQA — fully fp16 1-pass.
// BM=64 per CTA, 128 threads (4 warps, warp tile m16 x n64) -> 2 CTAs/SM.
// Q fragments hoisted to registers. smem = 2 x 32KB KV stages.
// ---------------------------------------------------------------------------
#define ST_KH 0
#define ST_VH 16384
#define KV_STAGE 32768
#define FL_SMEM (2 * KV_STAGE)

__global__ void __launch_bounds__(128) flash_attn_tc(
    const __half* __restrict__ qhi,
    const __half* __restrict__ kh, const __half* __restrict__ vh,
    __half* __restrict__ ohi)
{
    extern __shared__ char smem[];
    const uint32_t sb = smem_to_u32(smem);
    const int t = threadIdx.x, lane = t & 31, wid = t >> 5;
    const int qb = gridDim.x - 1 - blockIdx.x;   // heavy blocks first
    const int h = blockIdx.y, b = blockIdx.z;
    const int kvh = h >> 2;
    const int warp_m = wid * 16;                 // 4 warps cover 64 rows
    const int QSTR = NH * HD;
    const int KSTR = NKV * HD;

    // ---- stage Q (64x128 fp16 = 16KB) through stage-0 smem, hoist frags ----
    {
        const __half* qh = qhi + ((size_t)(b * SS + qb * 64)) * QSTR + h * HD;
#pragma unroll
        for (int i = 0; i < 8; i++) {
            int u = t + i * 128;
            int r = u >> 4, c = u & 15;
            *(uint4*)(smem + swz256(r, c)) =
                *(const uint4*)(qh + (size_t)r * QSTR + c * 8);
        }
    }
    __syncthreads();
    uint32_t qf[8][4];
#pragma unroll
    for (int ks = 0; ks < 8; ks++) {
        int ar = warp_m + (lane & 15);
        int ac = ks * 2 + (lane >> 4);
        ldsm_x4(qf[ks], sb + swz256(ar, ac));
    }
    __syncthreads();   // frags extracted; smem free for KV stages

    const int cr = t >> 4, cc = t & 15;          // 8 row-groups x 16 units
    const __half* kh0 = kh + ((size_t)(b * SS)) * KSTR + kvh * HD;
    const __half* vh0 = vh + ((size_t)(b * SS)) * KSTR + kvh * HD;

    auto issue_kv = [&](int kb) {
        uint32_t stage = sb + (uint32_t)(kb & 1) * KV_STAGE;
#pragma unroll
        for (int i = 0; i < 8; i++) {
            int r = cr + i * 8;
            size_t g = (size_t)(kb * 64 + r) * KSTR + cc * 8;
            uint32_t s = swz256(r, cc);
            cp_async16(stage + ST_KH + s, kh0 + g);
            cp_async16(stage + ST_VH + s, vh0 + g);
        }
    };

    issue_kv(0); CP_COMMIT();

    float m0 = -INFINITY, m1 = -INFINITY, l0 = 0.0f, l1 = 0.0f;
    float oacc[16][4];
#pragma unroll
    for (int i = 0; i < 16; i++)
#pragma unroll
        for (int j = 0; j < 4; j++) oacc[i][j] = 0.0f;

    const int row_lo = qb * 64 + warp_m + (lane >> 2);
    const int nkb = qb + 1;

    for (int kb = 0; kb < nkb; kb++) {
        CP_WAIT(0);
        __syncthreads();
        if (kb + 1 < nkb) { issue_kv(kb + 1); CP_COMMIT(); }

        const bool need_mask = (kb == qb);
        const uint32_t stage = sb + (uint32_t)(kb & 1) * KV_STAGE;

        float sacc[8][4];
#pragma unroll
        for (int i = 0; i < 8; i++)
#pragma unroll
            for (int j = 0; j < 4; j++) sacc[i][j] = 0.0f;

        // ---- S = Q K^T (fp16 1-pass, Q from registers) ----
#pragma unroll
        for (int ks = 0; ks < 8; ks++) {
#pragma unroll
            for (int np = 0; np < 4; np++) {
                uint32_t bh[4];
                int br = np * 16 + (lane & 7) + ((lane >> 4) & 1) * 8;
                int bc = ks * 2 + ((lane >> 3) & 1);
                ldsm_x4(bh, stage + ST_KH + swz256(br, bc));
                mma16816h(sacc[np * 2 + 0], qf[ks], bh[0], bh[1]);
                mma16816h(sacc[np * 2 + 1], qf[ks], bh[2], bh[3]);
            }
        }

        if (need_mask) {
#pragma unroll
            for (int nt = 0; nt < 8; nt++) {
                int col = kb * 64 + nt * 8 + (lane & 3) * 2;
#pragma unroll
                for (int j = 0; j < 4; j++) {
                    int cc2 = col + (j & 1);
                    int rr = row_lo + ((j >> 1) << 3);
                    if (cc2 > rr) sacc[nt][j] = -INFINITY;
                }
            }
        }

        float mt0 = -INFINITY, mt1 = -INFINITY;
#pragma unroll
        for (int nt = 0; nt < 8; nt++) {
            mt0 = fmaxf(mt0, fmaxf(sacc[nt][0], sacc[nt][1]));
            mt1 = fmaxf(mt1, fmaxf(sacc[nt][2], sacc[nt][3]));
        }
        mt0 = fmaxf(mt0, __shfl_xor_sync(0xffffffffu, mt0, 1));
        mt0 = fmaxf(mt0, __shfl_xor_sync(0xffffffffu, mt0, 2));
        mt1 = fmaxf(mt1, __shfl_xor_sync(0xffffffffu, mt1, 1));
        mt1 = fmaxf(mt1, __shfl_xor_sync(0xffffffffu, mt1, 2));

        float mn0 = fmaxf(m0, mt0), mn1 = fmaxf(m1, mt1);
        float sc0 = __expf(m0 - mn0), sc1 = __expf(m1 - mn1);
        m0 = mn0; m1 = mn1;

        float ps0 = 0.0f, ps1 = 0.0f;
#pragma unroll
        for (int nt = 0; nt < 8; nt++) {
            sacc[nt][0] = __expf(sacc[nt][0] - mn0);
            sacc[nt][1] = __expf(sacc[nt][1] - mn0);
            sacc[nt][2] = __expf(sacc[nt][2] - mn1);
            sacc[nt][3] = __expf(sacc[nt][3] - mn1);
            ps0 += sacc[nt][0] + sacc[nt][1];
            ps1 += sacc[nt][2] + sacc[nt][3];
        }
        ps0 += __shfl_xor_sync(0xffffffffu, ps0, 1);
        ps0 += __shfl_xor_sync(0xffffffffu, ps0, 2);
        ps1 += __shfl_xor_sync(0xffffffffu, ps1, 1);
        ps1 += __shfl_xor_sync(0xffffffffu, ps1, 2);
        l0 = l0 * sc0 + ps0;
        l1 = l1 * sc1 + ps1;

#pragma unroll
        for (int nt = 0; nt < 16; nt++) {
            oacc[nt][0] *= sc0; oacc[nt][1] *= sc0;
            oacc[nt][2] *= sc1; oacc[nt][3] *= sc1;
        }

        // ---- PV: fp16 1-pass (P hi x V hi) ----
#pragma unroll
        for (int ks = 0; ks < 4; ks++) {
            uint32_t phi[4];
            phi[0] = pack2h(sacc[2 * ks][0], sacc[2 * ks][1]);
            phi[1] = pack2h(sacc[2 * ks][2], sacc[2 * ks][3]);
            phi[2] = pack2h(sacc[2 * ks + 1][0], sacc[2 * ks + 1][1]);
            phi[3] = pack2h(sacc[2 * ks + 1][2], sacc[2 * ks + 1][3]);
#pragma unroll
            for (int dp = 0; dp < 8; dp++) {
                uint32_t vh4[4];
                int vr = ks * 16 + (lane & 7) + ((lane >> 3) & 1) * 8;
                int vc = dp * 2 + (lane >> 4);
                ldsm_x4_t(vh4, stage + ST_VH + swz256(vr, vc));
                mma16816h(oacc[dp * 2], phi, vh4[0], vh4[1]);
                mma16816h(oacc[dp * 2 + 1], phi, vh4[2], vh4[3]);
            }
        }
    }

    // ---- epilogue: write fp16 ----
    float il0 = 1.0f / l0, il1 = 1.0f / l1;
    __half* oh = ohi + ((size_t)(b * SS)) * QSTR + h * HD;
    int r0 = qb * 64 + warp_m + (lane >> 2);
#pragma unroll
    for (int nt = 0; nt < 16; nt++) {
        int dim = nt * 8 + (lane & 3) * 2;
        uint32_t h0 = pack2h(oacc[nt][0] * il0, oacc[nt][1] * il0);
        uint32_t h1 = pack2h(oacc[nt][2] * il1, oacc[nt][3] * il1);
        *(uint32_t*)&oh[(size_t)r0 * QSTR + dim] = h0;
        *(uint32_t*)&oh[(size_t)(r0 + 8) * QSTR + dim] = h1;
    }
}

// ---------------------------------------------------------------------------
extern "C" void kernel_launch(void* const* d_in, const int* in_sizes, int n_in,
                              void* d_out, int out_size)
{
    const float* hs  = (const float*)d_in[0];
    const float* q_w = (const float*)d_in[1];
    const float* k_w = (const float*)d_in[2];
    const float* v_w = (const float*)d_in[3];
    const float* o_w = (const float*)d_in[4];
    const float* qn  = (const float*)d_in[5];
    const float* kn  = (const float*)d_in[6];
    float* out = (float*)d_out;

    float* pqkv;
    __half *hsh, *qkvw, *owh, *pah, *pqh, *pkh, *pvh;
    cudaGetSymbolAddress((void**)&pqkv, g_qkv);
    cudaGetSymbolAddress((void**)&hsh, g_hs_hi);
    cudaGetSymbolAddress((void**)&qkvw, g_qkvw_hi);
    cudaGetSymbolAddress((void**)&owh, g_ow_hi);
    cudaGetSymbolAddress((void**)&pah, g_ahi);
    cudaGetSymbolAddress((void**)&pqh, g_qhi);
    cudaGetSymbolAddress((void**)&pkh, g_kh);
    cudaGetSymbolAddress((void**)&pvh, g_vh);

    const int M = BB * SS;     // 4096
    const int K = HH;          // 2048

    // fused operand conversion, one launch
    conv_all<<<18432, 256>>>(hs, q_w, k_w, v_w, o_w, hsh, qkvw, owh);

    cudaFuncSetAttribute(gemm_fp16, cudaFuncAttributeMaxDynamicSharedMemorySize,
                         GS_SMEM);

    // fused QKV projection: one GEMM, N = 3072 (1-pass fp16)
    gemm_fp16<<<dim3(NQKV / 128, M / 128), 512, GS_SMEM>>>(hsh, qkvw,
                                                           pqkv, M, NQKV, K);

    // fused rmsnorm+rope + V convert: one launch
    norm_split<<<dim3(M, NH + NKV + NKV), 128>>>(pqkv, qn, kn, pqh, pkh, pvh);

    // tensor-core causal flash attention (BM=64, 2 CTAs/SM)
    cudaFuncSetAttribute(flash_attn_tc, cudaFuncAttributeMaxDynamicSharedMemorySize,
                         FL_SMEM);
    flash_attn_tc<<<dim3(SS / 64, NH, BB), 128, FL_SMEM>>>(pqh, pkh, pvh, pah);

    // output projection (1-pass fp16)
    gemm_fp16<<<dim3(HH / 128, M / 128), 512, GS_SMEM>>>(pah, owh,
                                                         out, M, HH, K);
}